// round 1
// baseline (speedup 1.0000x reference)
#include <cuda_runtime.h>
#include <math.h>

#define E_   1024
#define NH   16
#define HD   64
#define WIN  256
#define BB   8
#define SS   1024
#define BS   (BB*SS)
#define FF   4096
#define SP   68   // padded smem row stride (floats) for attention tiles

// ---------------- scratch (static device globals: no allocation at runtime) ----
__device__ float g_qkin[BS*E_];
__device__ float g_q[BS*E_];
__device__ float g_k[BS*E_];
__device__ float g_v[BS*E_];
__device__ float g_ctx[BS*E_];
__device__ float g_tmp[BS*E_];
__device__ float g_x1[BS*E_];
__device__ float g_hid[(size_t)BS*FF];

// ---------------- RoPE on raw x -> qk_in -------------------------------------
__global__ __launch_bounds__(256) void rope_kernel(const float* __restrict__ x,
                                                   float* __restrict__ out)
{
    int tok = blockIdx.x;                    // 0..BS-1
    float pos = (float)(tok & (SS - 1));     // sequence position
    int base = tok * E_ + threadIdx.x * 4;
    int d = (threadIdx.x * 4) & (HD - 1);    // dim within head (4 consecutive, same half)
    const float* xp = &x[base];
    float4 xv = *(const float4*)xp;
    float res[4];
    const float LOG2_10000 = 13.287712379549449f;
#pragma unroll
    for (int i = 0; i < 4; i++) {
        int dd = d + i;
        int j = (dd < 32) ? dd : dd - 32;
        float fr = exp2f(-(float)j * (2.0f / 64.0f) * LOG2_10000);  // 10000^(-2j/64)
        float ang = pos * fr;
        float s, c;
        sincosf(ang, &s, &c);
        float v = ((const float*)&xv)[i];
        float other = (dd < 32) ? -xp[i + 32] : xp[i - 32];
        res[i] = v * c + other * s;
    }
    *(float4*)&out[base] = make_float4(res[0], res[1], res[2], res[3]);
}

// ---------------- generic NT GEMM: C[M,N] = A[M,K] @ W[N,K]^T + bias ----------
// ACT: 0 = none, 1 = exact GELU
template<int ACT>
__global__ __launch_bounds__(256) void gemm_kernel(
    const float* __restrict__ A, const float* __restrict__ W,
    const float* __restrict__ bias, float* __restrict__ C,
    int M, int N, int K)
{
    __shared__ float As[16][132];
    __shared__ float Bs[16][132];
    int m0 = blockIdx.y * 128;
    int n0 = blockIdx.x * 128;
    int t = threadIdx.x;
    int tx = t & 15, ty = t >> 4;

    float acc[8][8];
#pragma unroll
    for (int i = 0; i < 8; i++)
#pragma unroll
        for (int j = 0; j < 8; j++) acc[i][j] = 0.f;

    for (int k0 = 0; k0 < K; k0 += 16) {
#pragma unroll
        for (int i = 0; i < 2; i++) {
            int l = t + i * 256;
            int row = l >> 2;
            int c4 = (l & 3) * 4;
            float4 av = *(const float4*)&A[(size_t)(m0 + row) * K + k0 + c4];
            float4 wv = *(const float4*)&W[(size_t)(n0 + row) * K + k0 + c4];
            As[c4 + 0][row] = av.x; As[c4 + 1][row] = av.y;
            As[c4 + 2][row] = av.z; As[c4 + 3][row] = av.w;
            Bs[c4 + 0][row] = wv.x; Bs[c4 + 1][row] = wv.y;
            Bs[c4 + 2][row] = wv.z; Bs[c4 + 3][row] = wv.w;
        }
        __syncthreads();
#pragma unroll
        for (int kk = 0; kk < 16; kk++) {
            float a[8], b[8];
            *(float4*)&a[0] = *(const float4*)&As[kk][ty * 8];
            *(float4*)&a[4] = *(const float4*)&As[kk][ty * 8 + 4];
            *(float4*)&b[0] = *(const float4*)&Bs[kk][tx * 8];
            *(float4*)&b[4] = *(const float4*)&Bs[kk][tx * 8 + 4];
#pragma unroll
            for (int i = 0; i < 8; i++)
#pragma unroll
                for (int j = 0; j < 8; j++)
                    acc[i][j] += a[i] * b[j];
        }
        __syncthreads();
    }

#pragma unroll
    for (int i = 0; i < 8; i++) {
        size_t row = (size_t)(m0 + ty * 8 + i);
#pragma unroll
        for (int j = 0; j < 8; j++) {
            int col = n0 + tx * 8 + j;
            float v = acc[i][j] + bias[col];
            if (ACT == 1)
                v = 0.5f * v * (1.0f + erff(v * 0.70710678118654752f));
            acc[i][j] = v;
        }
        *(float4*)&C[row * N + n0 + tx * 8] =
            make_float4(acc[i][0], acc[i][1], acc[i][2], acc[i][3]);
        *(float4*)&C[row * N + n0 + tx * 8 + 4] =
            make_float4(acc[i][4], acc[i][5], acc[i][6], acc[i][7]);
    }
}

// ---------------- sliding-window attention (flash-style, online softmax) -----
__global__ __launch_bounds__(256) void attn_kernel(
    const float* __restrict__ q, const float* __restrict__ k,
    const float* __restrict__ v, float* __restrict__ out)
{
    extern __shared__ float sm[];
    float* q_s = sm;                 // [64][SP]
    float* k_s = q_s + 64 * SP;      // [64][SP]
    float* v_s = k_s + 64 * SP;      // [64][SP]
    float* p_s = v_s + 64 * SP;      // [64][SP]

    int b = blockIdx.z, h = blockIdx.y;
    int q0 = blockIdx.x * 64;
    int t = threadIdx.x;
    int tq = t >> 4, tk = t & 15;

    // load Q tile
#pragma unroll
    for (int i = 0; i < 4; i++) {
        int l = t + i * 256;
        int r = l >> 4;
        int c = (l & 15) * 4;
        *(float4*)&q_s[r * SP + c] =
            *(const float4*)&q[((size_t)(b * SS + q0 + r)) * E_ + h * HD + c];
    }

    float m[4], lsum[4], acc[4][4];
#pragma unroll
    for (int i = 0; i < 4; i++) {
        m[i] = -1e30f; lsum[i] = 0.f;
#pragma unroll
        for (int j = 0; j < 4; j++) acc[i][j] = 0.f;
    }

    int kstart = q0 - WIN; if (kstart < 0) kstart = 0;
    int kend = q0 + 64 + WIN; if (kend > SS) kend = SS;
    const float scale = 0.125f;   // 1/sqrt(64)

    for (int kb = kstart; kb < kend; kb += 64) {
        __syncthreads();   // protect k_s/v_s/p_s reuse (and q_s first pass)
#pragma unroll
        for (int i = 0; i < 4; i++) {
            int l = t + i * 256;
            int r = l >> 4;
            int c = (l & 15) * 4;
            size_t gi = ((size_t)(b * SS + kb + r)) * E_ + h * HD + c;
            *(float4*)&k_s[r * SP + c] = *(const float4*)&k[gi];
            *(float4*)&v_s[r * SP + c] = *(const float4*)&v[gi];
        }
        __syncthreads();

        // scores: 4x4 per thread
        float s[4][4];
#pragma unroll
        for (int i = 0; i < 4; i++)
#pragma unroll
            for (int j = 0; j < 4; j++) s[i][j] = 0.f;
#pragma unroll
        for (int d4 = 0; d4 < 16; d4++) {
            float4 qv[4], kv[4];
#pragma unroll
            for (int i = 0; i < 4; i++)
                qv[i] = *(const float4*)&q_s[(tq * 4 + i) * SP + d4 * 4];
#pragma unroll
            for (int j = 0; j < 4; j++)
                kv[j] = *(const float4*)&k_s[(tk * 4 + j) * SP + d4 * 4];
#pragma unroll
            for (int i = 0; i < 4; i++)
#pragma unroll
                for (int j = 0; j < 4; j++)
                    s[i][j] += qv[i].x * kv[j].x + qv[i].y * kv[j].y +
                               qv[i].z * kv[j].z + qv[i].w * kv[j].w;
        }

        // mask + online softmax update
#pragma unroll
        for (int i = 0; i < 4; i++) {
            int qi = q0 + tq * 4 + i;
            float rmax = -1e30f;
#pragma unroll
            for (int j = 0; j < 4; j++) {
                int diff = qi - (kb + tk * 4 + j);
                bool ok = (diff <= WIN) && (diff >= -WIN);
                s[i][j] = ok ? s[i][j] * scale : -1e30f;
                rmax = fmaxf(rmax, s[i][j]);
            }
            rmax = fmaxf(rmax, __shfl_xor_sync(0xffffffffu, rmax, 1));
            rmax = fmaxf(rmax, __shfl_xor_sync(0xffffffffu, rmax, 2));
            rmax = fmaxf(rmax, __shfl_xor_sync(0xffffffffu, rmax, 4));
            rmax = fmaxf(rmax, __shfl_xor_sync(0xffffffffu, rmax, 8));
            float mnew = fmaxf(m[i], rmax);
            float corr = expf(m[i] - mnew);
            float rsum = 0.f;
#pragma unroll
            for (int j = 0; j < 4; j++) {
                float p = (s[i][j] > -1e29f) ? expf(s[i][j] - mnew) : 0.f;
                p_s[(tq * 4 + i) * SP + tk * 4 + j] = p;
                rsum += p;
            }
            rsum += __shfl_xor_sync(0xffffffffu, rsum, 1);
            rsum += __shfl_xor_sync(0xffffffffu, rsum, 2);
            rsum += __shfl_xor_sync(0xffffffffu, rsum, 4);
            rsum += __shfl_xor_sync(0xffffffffu, rsum, 8);
            m[i] = mnew;
            lsum[i] = lsum[i] * corr + rsum;
#pragma unroll
            for (int j = 0; j < 4; j++) acc[i][j] *= corr;
        }
        __syncthreads();

        // acc += P @ V  (thread owns rows tq*4.., dims tk*4..)
#pragma unroll 4
        for (int kk = 0; kk < 64; kk++) {
            float4 vv = *(const float4*)&v_s[kk * SP + tk * 4];
#pragma unroll
            for (int i = 0; i < 4; i++) {
                float p = p_s[(tq * 4 + i) * SP + kk];
                acc[i][0] += p * vv.x; acc[i][1] += p * vv.y;
                acc[i][2] += p * vv.z; acc[i][3] += p * vv.w;
            }
        }
    }

#pragma unroll
    for (int i = 0; i < 4; i++) {
        float inv = 1.f / lsum[i];
        size_t o = ((size_t)(b * SS + q0 + tq * 4 + i)) * E_ + h * HD + tk * 4;
        *(float4*)&out[o] = make_float4(acc[i][0] * inv, acc[i][1] * inv,
                                        acc[i][2] * inv, acc[i][3] * inv);
    }
}

// ---------------- residual add + LayerNorm ------------------------------------
__global__ __launch_bounds__(256) void add_ln_kernel(
    const float* __restrict__ a, const float* __restrict__ r,
    const float* __restrict__ g, const float* __restrict__ be,
    float* __restrict__ out)
{
    int row = blockIdx.x;
    int t = threadIdx.x;
    size_t base = (size_t)row * E_;
    float4 av = *(const float4*)&a[base + t * 4];
    float4 rv = *(const float4*)&r[base + t * 4];
    float v0 = av.x + rv.x, v1 = av.y + rv.y, v2 = av.z + rv.z, v3 = av.w + rv.w;
    float sum = v0 + v1 + v2 + v3;
    float sq = v0 * v0 + v1 * v1 + v2 * v2 + v3 * v3;
#pragma unroll
    for (int off = 16; off; off >>= 1) {
        sum += __shfl_xor_sync(0xffffffffu, sum, off);
        sq  += __shfl_xor_sync(0xffffffffu, sq, off);
    }
    __shared__ float ss[8], sq2[8], stat[2];
    int w = t >> 5;
    if ((t & 31) == 0) { ss[w] = sum; sq2[w] = sq; }
    __syncthreads();
    if (t == 0) {
        float S1 = 0.f, S2 = 0.f;
        for (int i = 0; i < 8; i++) { S1 += ss[i]; S2 += sq2[i]; }
        float mean = S1 * (1.0f / E_);
        float var = S2 * (1.0f / E_) - mean * mean;
        stat[0] = mean;
        stat[1] = rsqrtf(var + 1e-5f);
    }
    __syncthreads();
    float mean = stat[0], rstd = stat[1];
    float4 gv = *(const float4*)&g[t * 4];
    float4 bv = *(const float4*)&be[t * 4];
    float4 o;
    o.x = (v0 - mean) * rstd * gv.x + bv.x;
    o.y = (v1 - mean) * rstd * gv.y + bv.y;
    o.z = (v2 - mean) * rstd * gv.z + bv.z;
    o.w = (v3 - mean) * rstd * gv.w + bv.w;
    *(float4*)&out[base + t * 4] = o;
}

// ---------------- launch -------------------------------------------------------
extern "C" void kernel_launch(void* const* d_in, const int* in_sizes, int n_in,
                              void* d_out, int out_size)
{
    (void)in_sizes; (void)n_in; (void)out_size;
    const float* x    = (const float*)d_in[0];
    const float* ipw  = (const float*)d_in[1];
    const float* ipb  = (const float*)d_in[2];
    const float* opw  = (const float*)d_in[3];
    const float* opb  = (const float*)d_in[4];
    const float* ln1g = (const float*)d_in[5];
    const float* ln1b = (const float*)d_in[6];
    const float* w1   = (const float*)d_in[7];
    const float* b1   = (const float*)d_in[8];
    const float* w2   = (const float*)d_in[9];
    const float* b2   = (const float*)d_in[10];
    const float* ln2g = (const float*)d_in[11];
    const float* ln2b = (const float*)d_in[12];
    float* out = (float*)d_out;

    float *qkin, *qb, *kb, *vb, *ctx, *tmp, *x1, *hid;
    cudaGetSymbolAddress((void**)&qkin, g_qkin);
    cudaGetSymbolAddress((void**)&qb,   g_q);
    cudaGetSymbolAddress((void**)&kb,   g_k);
    cudaGetSymbolAddress((void**)&vb,   g_v);
    cudaGetSymbolAddress((void**)&ctx,  g_ctx);
    cudaGetSymbolAddress((void**)&tmp,  g_tmp);
    cudaGetSymbolAddress((void**)&x1,   g_x1);
    cudaGetSymbolAddress((void**)&hid,  g_hid);

    int attn_smem = 4 * 64 * SP * (int)sizeof(float);   // 69632 B
    cudaFuncSetAttribute(attn_kernel,
                         cudaFuncAttributeMaxDynamicSharedMemorySize, attn_smem);

    // 1) RoPE(x) -> qk_in
    rope_kernel<<<BS, 256>>>(x, qkin);

    // 2) Q = qk_in @ Wq^T, K = qk_in @ Wk^T, V = x @ Wv^T
    gemm_kernel<0><<<dim3(E_ / 128, BS / 128), 256>>>(qkin, ipw,                      ipb,          qb, BS, E_, E_);
    gemm_kernel<0><<<dim3(E_ / 128, BS / 128), 256>>>(qkin, ipw + (size_t)E_ * E_,    ipb + E_,     kb, BS, E_, E_);
    gemm_kernel<0><<<dim3(E_ / 128, BS / 128), 256>>>(x,    ipw + (size_t)2 * E_ * E_, ipb + 2 * E_, vb, BS, E_, E_);

    // 3) sliding-window attention -> ctx
    attn_kernel<<<dim3(SS / 64, NH, BB), 256, attn_smem>>>(qb, kb, vb, ctx);

    // 4) out-proj, residual + LN1 -> x1
    gemm_kernel<0><<<dim3(E_ / 128, BS / 128), 256>>>(ctx, opw, opb, tmp, BS, E_, E_);
    add_ln_kernel<<<BS, 256>>>(x, tmp, ln1g, ln1b, x1);

    // 5) FFN: gelu(x1 @ W1^T + b1) @ W2^T + b2, residual + LN2 -> out
    gemm_kernel<1><<<dim3(FF / 128, BS / 128), 256>>>(x1,  w1, b1, hid, BS, FF, E_);
    gemm_kernel<0><<<dim3(E_ / 128, BS / 128), 256>>>(hid, w2, b2, tmp, BS, E_, FF);
    add_ln_kernel<<<BS, 256>>>(x1, tmp, ln2g, ln2b, out);
}

// round 2
// speedup vs baseline: 1.0193x; 1.0193x over previous
#include <cuda_runtime.h>
#include <math.h>

#define E_   1024
#define NH   16
#define HD   64
#define WIN  256
#define BB   8
#define SS   1024
#define BS   (BB*SS)
#define FF   4096
#define SP   68   // padded smem row stride (floats) for attention tiles

// ---------------- scratch (static device globals: no allocation at runtime) ----
__device__ float g_qkin[BS*E_];
__device__ float g_q[BS*E_];
__device__ float g_k[BS*E_];
__device__ float g_v[BS*E_];
__device__ float g_ctx[BS*E_];
__device__ float g_tmp[BS*E_];
__device__ float g_x1[BS*E_];
__device__ float g_hid[(size_t)BS*FF];

// ---------------- packed f32x2 helpers ----------------------------------------
__device__ __forceinline__ void ffma2(unsigned long long& d,
                                      unsigned long long a,
                                      unsigned long long b)
{
    asm("fma.rn.f32x2 %0, %1, %2, %0;" : "+l"(d) : "l"(a), "l"(b));
}
__device__ __forceinline__ unsigned long long pack2(float lo, float hi)
{
    unsigned long long r;
    asm("mov.b64 %0, {%1, %2};" : "=l"(r) : "f"(lo), "f"(hi));
    return r;
}
__device__ __forceinline__ unsigned long long dup2(float v)
{
    unsigned long long r;
    asm("mov.b64 %0, {%1, %1};" : "=l"(r) : "f"(v));
    return r;
}
__device__ __forceinline__ void unpack2(unsigned long long v, float& lo, float& hi)
{
    asm("mov.b64 {%0, %1}, %2;" : "=f"(lo), "=f"(hi) : "l"(v));
}

// ---------------- RoPE on raw x -> qk_in -------------------------------------
__global__ __launch_bounds__(256) void rope_kernel(const float* __restrict__ x,
                                                   float* __restrict__ out)
{
    int tok = blockIdx.x;                    // 0..BS-1
    float pos = (float)(tok & (SS - 1));     // sequence position
    int base = tok * E_ + threadIdx.x * 4;
    int d = (threadIdx.x * 4) & (HD - 1);    // dim within head (4 consecutive, same half)
    const float* xp = &x[base];
    float4 xv = *(const float4*)xp;
    float res[4];
    const float LOG2_10000 = 13.287712379549449f;
#pragma unroll
    for (int i = 0; i < 4; i++) {
        int dd = d + i;
        int j = (dd < 32) ? dd : dd - 32;
        float fr = exp2f(-(float)j * (2.0f / 64.0f) * LOG2_10000);  // 10000^(-2j/64)
        float ang = pos * fr;
        float s, c;
        sincosf(ang, &s, &c);
        float v = ((const float*)&xv)[i];
        float other = (dd < 32) ? -xp[i + 32] : xp[i - 32];
        res[i] = v * c + other * s;
    }
    *(float4*)&out[base] = make_float4(res[0], res[1], res[2], res[3]);
}

// ---------------- generic NT GEMM: C[M,N] = A[M,K] @ W[N,K]^T + bias ----------
// 128x128 tile, 256 threads, 8x8 per-thread via packed f32x2 FFMA2.
// Double-buffered smem, register prefetch, single __syncthreads per k-tile.
// ACT: 0 = none, 1 = exact GELU
template<int ACT>
__global__ __launch_bounds__(256, 2) void gemm_kernel(
    const float* __restrict__ A, const float* __restrict__ W,
    const float* __restrict__ bias, float* __restrict__ C,
    int M, int N, int K)
{
    __shared__ float As[2][16][132];
    __shared__ float Bs[2][16][132];
    int m0 = blockIdx.y * 128;
    int n0 = blockIdx.x * 128;
    int t = threadIdx.x;
    int tx = t & 15, ty = t >> 4;

    // loader lane mapping (2 float4 per matrix per thread per k-tile)
    int l0 = t, l1 = t + 256;
    int row0 = l0 >> 2, c40 = (l0 & 3) * 4;
    int row1 = l1 >> 2, c41 = (l1 & 3) * 4;

    const float* Ar0 = &A[(size_t)(m0 + row0) * K + c40];
    const float* Ar1 = &A[(size_t)(m0 + row1) * K + c41];
    const float* Wr0 = &W[(size_t)(n0 + row0) * K + c40];
    const float* Wr1 = &W[(size_t)(n0 + row1) * K + c41];

    unsigned long long acc2[8][4];
#pragma unroll
    for (int i = 0; i < 8; i++)
#pragma unroll
        for (int j = 0; j < 4; j++) acc2[i][j] = 0ull;

    // prologue: load first k-tile
    float4 av0 = *(const float4*)Ar0;
    float4 av1 = *(const float4*)Ar1;
    float4 wv0 = *(const float4*)Wr0;
    float4 wv1 = *(const float4*)Wr1;

    As[0][c40 + 0][row0] = av0.x; As[0][c40 + 1][row0] = av0.y;
    As[0][c40 + 2][row0] = av0.z; As[0][c40 + 3][row0] = av0.w;
    As[0][c41 + 0][row1] = av1.x; As[0][c41 + 1][row1] = av1.y;
    As[0][c41 + 2][row1] = av1.z; As[0][c41 + 3][row1] = av1.w;
    Bs[0][c40 + 0][row0] = wv0.x; Bs[0][c40 + 1][row0] = wv0.y;
    Bs[0][c40 + 2][row0] = wv0.z; Bs[0][c40 + 3][row0] = wv0.w;
    Bs[0][c41 + 0][row1] = wv1.x; Bs[0][c41 + 1][row1] = wv1.y;
    Bs[0][c41 + 2][row1] = wv1.z; Bs[0][c41 + 3][row1] = wv1.w;
    __syncthreads();

    int nt = K >> 4;
    for (int kt = 0; kt < nt; kt++) {
        int cur = kt & 1;
        bool more = (kt + 1) < nt;
        if (more) {
            int ko = (kt + 1) << 4;
            av0 = *(const float4*)(Ar0 + ko);
            av1 = *(const float4*)(Ar1 + ko);
            wv0 = *(const float4*)(Wr0 + ko);
            wv1 = *(const float4*)(Wr1 + ko);
        }

#pragma unroll
        for (int kk = 0; kk < 16; kk++) {
            float a[8], b[8];
            *(float4*)&a[0] = *(const float4*)&As[cur][kk][ty * 8];
            *(float4*)&a[4] = *(const float4*)&As[cur][kk][ty * 8 + 4];
            *(float4*)&b[0] = *(const float4*)&Bs[cur][kk][tx * 8];
            *(float4*)&b[4] = *(const float4*)&Bs[cur][kk][tx * 8 + 4];
            unsigned long long b2[4];
#pragma unroll
            for (int p = 0; p < 4; p++) b2[p] = pack2(b[2 * p], b[2 * p + 1]);
#pragma unroll
            for (int i = 0; i < 8; i++) {
                unsigned long long a2 = dup2(a[i]);
#pragma unroll
                for (int p = 0; p < 4; p++) ffma2(acc2[i][p], a2, b2[p]);
            }
        }

        if (more) {
            int nb = (kt + 1) & 1;
            As[nb][c40 + 0][row0] = av0.x; As[nb][c40 + 1][row0] = av0.y;
            As[nb][c40 + 2][row0] = av0.z; As[nb][c40 + 3][row0] = av0.w;
            As[nb][c41 + 0][row1] = av1.x; As[nb][c41 + 1][row1] = av1.y;
            As[nb][c41 + 2][row1] = av1.z; As[nb][c41 + 3][row1] = av1.w;
            Bs[nb][c40 + 0][row0] = wv0.x; Bs[nb][c40 + 1][row0] = wv0.y;
            Bs[nb][c40 + 2][row0] = wv0.z; Bs[nb][c40 + 3][row0] = wv0.w;
            Bs[nb][c41 + 0][row1] = wv1.x; Bs[nb][c41 + 1][row1] = wv1.y;
            Bs[nb][c41 + 2][row1] = wv1.z; Bs[nb][c41 + 3][row1] = wv1.w;
        }
        __syncthreads();
    }

#pragma unroll
    for (int i = 0; i < 8; i++) {
        size_t row = (size_t)(m0 + ty * 8 + i);
        float o[8];
#pragma unroll
        for (int p = 0; p < 4; p++) {
            float lo, hi;
            unpack2(acc2[i][p], lo, hi);
            o[2 * p] = lo; o[2 * p + 1] = hi;
        }
#pragma unroll
        for (int j = 0; j < 8; j++) {
            int col = n0 + tx * 8 + j;
            float v = o[j] + bias[col];
            if (ACT == 1)
                v = 0.5f * v * (1.0f + erff(v * 0.70710678118654752f));
            o[j] = v;
        }
        *(float4*)&C[row * N + n0 + tx * 8] =
            make_float4(o[0], o[1], o[2], o[3]);
        *(float4*)&C[row * N + n0 + tx * 8 + 4] =
            make_float4(o[4], o[5], o[6], o[7]);
    }
}

// ---------------- sliding-window attention (flash-style, online softmax) -----
__global__ __launch_bounds__(256) void attn_kernel(
    const float* __restrict__ q, const float* __restrict__ k,
    const float* __restrict__ v, float* __restrict__ out)
{
    extern __shared__ float sm[];
    float* q_s = sm;                 // [64][SP]
    float* k_s = q_s + 64 * SP;      // [64][SP]
    float* v_s = k_s + 64 * SP;      // [64][SP]
    float* p_s = v_s + 64 * SP;      // [64][SP]

    int b = blockIdx.z, h = blockIdx.y;
    int q0 = blockIdx.x * 64;
    int t = threadIdx.x;
    int tq = t >> 4, tk = t & 15;

    // load Q tile
#pragma unroll
    for (int i = 0; i < 4; i++) {
        int l = t + i * 256;
        int r = l >> 4;
        int c = (l & 15) * 4;
        *(float4*)&q_s[r * SP + c] =
            *(const float4*)&q[((size_t)(b * SS + q0 + r)) * E_ + h * HD + c];
    }

    float m[4], lsum[4], acc[4][4];
#pragma unroll
    for (int i = 0; i < 4; i++) {
        m[i] = -1e30f; lsum[i] = 0.f;
#pragma unroll
        for (int j = 0; j < 4; j++) acc[i][j] = 0.f;
    }

    int kstart = q0 - WIN; if (kstart < 0) kstart = 0;
    int kend = q0 + 64 + WIN; if (kend > SS) kend = SS;
    const float scale = 0.125f;   // 1/sqrt(64)

    for (int kb = kstart; kb < kend; kb += 64) {
        __syncthreads();   // protect k_s/v_s/p_s reuse (and q_s first pass)
#pragma unroll
        for (int i = 0; i < 4; i++) {
            int l = t + i * 256;
            int r = l >> 4;
            int c = (l & 15) * 4;
            size_t gi = ((size_t)(b * SS + kb + r)) * E_ + h * HD + c;
            *(float4*)&k_s[r * SP + c] = *(const float4*)&k[gi];
            *(float4*)&v_s[r * SP + c] = *(const float4*)&v[gi];
        }
        __syncthreads();

        // scores: 4x4 per thread
        float s[4][4];
#pragma unroll
        for (int i = 0; i < 4; i++)
#pragma unroll
            for (int j = 0; j < 4; j++) s[i][j] = 0.f;
#pragma unroll
        for (int d4 = 0; d4 < 16; d4++) {
            float4 qv[4], kv[4];
#pragma unroll
            for (int i = 0; i < 4; i++)
                qv[i] = *(const float4*)&q_s[(tq * 4 + i) * SP + d4 * 4];
#pragma unroll
            for (int j = 0; j < 4; j++)
                kv[j] = *(const float4*)&k_s[(tk * 4 + j) * SP + d4 * 4];
#pragma unroll
            for (int i = 0; i < 4; i++)
#pragma unroll
                for (int j = 0; j < 4; j++)
                    s[i][j] += qv[i].x * kv[j].x + qv[i].y * kv[j].y +
                               qv[i].z * kv[j].z + qv[i].w * kv[j].w;
        }

        // mask + online softmax update
#pragma unroll
        for (int i = 0; i < 4; i++) {
            int qi = q0 + tq * 4 + i;
            float rmax = -1e30f;
#pragma unroll
            for (int j = 0; j < 4; j++) {
                int diff = qi - (kb + tk * 4 + j);
                bool ok = (diff <= WIN) && (diff >= -WIN);
                s[i][j] = ok ? s[i][j] * scale : -1e30f;
                rmax = fmaxf(rmax, s[i][j]);
            }
            rmax = fmaxf(rmax, __shfl_xor_sync(0xffffffffu, rmax, 1));
            rmax = fmaxf(rmax, __shfl_xor_sync(0xffffffffu, rmax, 2));
            rmax = fmaxf(rmax, __shfl_xor_sync(0xffffffffu, rmax, 4));
            rmax = fmaxf(rmax, __shfl_xor_sync(0xffffffffu, rmax, 8));
            float mnew = fmaxf(m[i], rmax);
            float corr = expf(m[i] - mnew);
            float rsum = 0.f;
#pragma unroll
            for (int j = 0; j < 4; j++) {
                float p = (s[i][j] > -1e29f) ? expf(s[i][j] - mnew) : 0.f;
                p_s[(tq * 4 + i) * SP + tk * 4 + j] = p;
                rsum += p;
            }
            rsum += __shfl_xor_sync(0xffffffffu, rsum, 1);
            rsum += __shfl_xor_sync(0xffffffffu, rsum, 2);
            rsum += __shfl_xor_sync(0xffffffffu, rsum, 4);
            rsum += __shfl_xor_sync(0xffffffffu, rsum, 8);
            m[i] = mnew;
            lsum[i] = lsum[i] * corr + rsum;
#pragma unroll
            for (int j = 0; j < 4; j++) acc[i][j] *= corr;
        }
        __syncthreads();

        // acc += P @ V  (thread owns rows tq*4.., dims tk*4..)
#pragma unroll 4
        for (int kk = 0; kk < 64; kk++) {
            float4 vv = *(const float4*)&v_s[kk * SP + tk * 4];
#pragma unroll
            for (int i = 0; i < 4; i++) {
                float p = p_s[(tq * 4 + i) * SP + kk];
                acc[i][0] += p * vv.x; acc[i][1] += p * vv.y;
                acc[i][2] += p * vv.z; acc[i][3] += p * vv.w;
            }
        }
    }

#pragma unroll
    for (int i = 0; i < 4; i++) {
        float inv = 1.f / lsum[i];
        size_t o = ((size_t)(b * SS + q0 + tq * 4 + i)) * E_ + h * HD + tk * 4;
        *(float4*)&out[o] = make_float4(acc[i][0] * inv, acc[i][1] * inv,
                                        acc[i][2] * inv, acc[i][3] * inv);
    }
}

// ---------------- residual add + LayerNorm ------------------------------------
__global__ __launch_bounds__(256) void add_ln_kernel(
    const float* __restrict__ a, const float* __restrict__ r,
    const float* __restrict__ g, const float* __restrict__ be,
    float* __restrict__ out)
{
    int row = blockIdx.x;
    int t = threadIdx.x;
    size_t base = (size_t)row * E_;
    float4 av = *(const float4*)&a[base + t * 4];
    float4 rv = *(const float4*)&r[base + t * 4];
    float v0 = av.x + rv.x, v1 = av.y + rv.y, v2 = av.z + rv.z, v3 = av.w + rv.w;
    float sum = v0 + v1 + v2 + v3;
    float sq = v0 * v0 + v1 * v1 + v2 * v2 + v3 * v3;
#pragma unroll
    for (int off = 16; off; off >>= 1) {
        sum += __shfl_xor_sync(0xffffffffu, sum, off);
        sq  += __shfl_xor_sync(0xffffffffu, sq, off);
    }
    __shared__ float ss[8], sq2[8], stat[2];
    int w = t >> 5;
    if ((t & 31) == 0) { ss[w] = sum; sq2[w] = sq; }
    __syncthreads();
    if (t == 0) {
        float S1 = 0.f, S2 = 0.f;
        for (int i = 0; i < 8; i++) { S1 += ss[i]; S2 += sq2[i]; }
        float mean = S1 * (1.0f / E_);
        float var = S2 * (1.0f / E_) - mean * mean;
        stat[0] = mean;
        stat[1] = rsqrtf(var + 1e-5f);
    }
    __syncthreads();
    float mean = stat[0], rstd = stat[1];
    float4 gv = *(const float4*)&g[t * 4];
    float4 bv = *(const float4*)&be[t * 4];
    float4 o;
    o.x = (v0 - mean) * rstd * gv.x + bv.x;
    o.y = (v1 - mean) * rstd * gv.y + bv.y;
    o.z = (v2 - mean) * rstd * gv.z + bv.z;
    o.w = (v3 - mean) * rstd * gv.w + bv.w;
    *(float4*)&out[base + t * 4] = o;
}

// ---------------- launch -------------------------------------------------------
extern "C" void kernel_launch(void* const* d_in, const int* in_sizes, int n_in,
                              void* d_out, int out_size)
{
    (void)in_sizes; (void)n_in; (void)out_size;
    const float* x    = (const float*)d_in[0];
    const float* ipw  = (const float*)d_in[1];
    const float* ipb  = (const float*)d_in[2];
    const float* opw  = (const float*)d_in[3];
    const float* opb  = (const float*)d_in[4];
    const float* ln1g = (const float*)d_in[5];
    const float* ln1b = (const float*)d_in[6];
    const float* w1   = (const float*)d_in[7];
    const float* b1   = (const float*)d_in[8];
    const float* w2   = (const float*)d_in[9];
    const float* b2   = (const float*)d_in[10];
    const float* ln2g = (const float*)d_in[11];
    const float* ln2b = (const float*)d_in[12];
    float* out = (float*)d_out;

    float *qkin, *qb, *kb, *vb, *ctx, *tmp, *x1, *hid;
    cudaGetSymbolAddress((void**)&qkin, g_qkin);
    cudaGetSymbolAddress((void**)&qb,   g_q);
    cudaGetSymbolAddress((void**)&kb,   g_k);
    cudaGetSymbolAddress((void**)&vb,   g_v);
    cudaGetSymbolAddress((void**)&ctx,  g_ctx);
    cudaGetSymbolAddress((void**)&tmp,  g_tmp);
    cudaGetSymbolAddress((void**)&x1,   g_x1);
    cudaGetSymbolAddress((void**)&hid,  g_hid);

    int attn_smem = 4 * 64 * SP * (int)sizeof(float);   // 69632 B
    cudaFuncSetAttribute(attn_kernel,
                         cudaFuncAttributeMaxDynamicSharedMemorySize, attn_smem);

    // 1) RoPE(x) -> qk_in
    rope_kernel<<<BS, 256>>>(x, qkin);

    // 2) Q = qk_in @ Wq^T, K = qk_in @ Wk^T, V = x @ Wv^T
    gemm_kernel<0><<<dim3(E_ / 128, BS / 128), 256>>>(qkin, ipw,                      ipb,          qb, BS, E_, E_);
    gemm_kernel<0><<<dim3(E_ / 128, BS / 128), 256>>>(qkin, ipw + (size_t)E_ * E_,    ipb + E_,     kb, BS, E_, E_);
    gemm_kernel<0><<<dim3(E_ / 128, BS / 128), 256>>>(x,    ipw + (size_t)2 * E_ * E_, ipb + 2 * E_, vb, BS, E_, E_);

    // 3) sliding-window attention -> ctx
    attn_kernel<<<dim3(SS / 64, NH, BB), 256, attn_smem>>>(qb, kb, vb, ctx);

    // 4) out-proj, residual + LN1 -> x1
    gemm_kernel<0><<<dim3(E_ / 128, BS / 128), 256>>>(ctx, opw, opb, tmp, BS, E_, E_);
    add_ln_kernel<<<BS, 256>>>(x, tmp, ln1g, ln1b, x1);

    // 5) FFN: gelu(x1 @ W1^T + b1) @ W2^T + b2, residual + LN2 -> out
    gemm_kernel<1><<<dim3(FF / 128, BS / 128), 256>>>(x1,  w1, b1, hid, BS, FF, E_);
    gemm_kernel<0><<<dim3(E_ / 128, BS / 128), 256>>>(hid, w2, b2, tmp, BS, E_, FF);
    add_ln_kernel<<<BS, 256>>>(x1, tmp, ln2g, ln2b, out);
}

// round 4
// speedup vs baseline: 1.9999x; 1.9621x over previous
#include <cuda_runtime.h>
#include <cuda_bf16.h>
#include <math.h>
#include <stdint.h>

#define E_   1024
#define NH   16
#define HD   64
#define WIN  256
#define BB   8
#define SS   1024
#define BS   (BB*SS)
#define FF   4096
#define SP   68   // padded smem row stride (floats) for attention tiles

// ---------------- fp32 scratch -------------------------------------------------
__device__ float g_qkin[BS*E_];
__device__ float g_q[BS*E_];
__device__ float g_k[BS*E_];
__device__ float g_v[BS*E_];
__device__ float g_ctx[BS*E_];
__device__ float g_tmp[BS*E_];
__device__ float g_x1[BS*E_];
__device__ float g_hid[(size_t)BS*FF];

// ---------------- bf16 split scratch -------------------------------------------
__device__ __nv_bfloat16 g_a1h[BS*E_], g_a1l[BS*E_];
__device__ __nv_bfloat16 g_a2h[BS*E_], g_a2l[BS*E_];
__device__ __nv_bfloat16 g_hh[(size_t)BS*FF], g_hl[(size_t)BS*FF];
__device__ __nv_bfloat16 g_wih[3*E_*E_], g_wil[3*E_*E_];
__device__ __nv_bfloat16 g_woh[E_*E_],   g_wol[E_*E_];
__device__ __nv_bfloat16 g_w1h[FF*E_],   g_w1l[FF*E_];
__device__ __nv_bfloat16 g_w2h[FF*E_],   g_w2l[FF*E_];

// ---------------- helpers -------------------------------------------------------
__device__ __forceinline__ uint32_t smem_u32(const void* p) {
    uint32_t a;
    asm("{ .reg .u64 t; cvta.to.shared.u64 t, %1; cvt.u32.u64 %0, t; }" : "=r"(a) : "l"(p));
    return a;
}
__device__ __forceinline__ void cp16(uint32_t dst, const void* src) {
    asm volatile("cp.async.cg.shared.global [%0], [%1], 16;" :: "r"(dst), "l"(src));
}
__device__ __forceinline__ void cp_commit() { asm volatile("cp.async.commit_group;"); }
__device__ __forceinline__ void cp_wait0()  { asm volatile("cp.async.wait_group 0;" ::: "memory"); }

__device__ __forceinline__ void ldm_x4(uint32_t addr, uint32_t& r0, uint32_t& r1,
                                       uint32_t& r2, uint32_t& r3) {
    asm volatile("ldmatrix.sync.aligned.m8n8.x4.shared.b16 {%0,%1,%2,%3}, [%4];"
                 : "=r"(r0), "=r"(r1), "=r"(r2), "=r"(r3) : "r"(addr));
}
__device__ __forceinline__ void mma16816(float* c, const uint32_t* a, const uint32_t* b) {
    asm volatile(
        "mma.sync.aligned.m16n8k16.row.col.f32.bf16.bf16.f32 "
        "{%0,%1,%2,%3}, {%4,%5,%6,%7}, {%8,%9}, {%0,%1,%2,%3};"
        : "+f"(c[0]), "+f"(c[1]), "+f"(c[2]), "+f"(c[3])
        : "r"(a[0]), "r"(a[1]), "r"(a[2]), "r"(a[3]), "r"(b[0]), "r"(b[1]));
}

// ---------------- split fp32 -> bf16 hi/lo -------------------------------------
__global__ __launch_bounds__(256) void split_kernel(const float* __restrict__ src,
                                                    __nv_bfloat16* __restrict__ hi,
                                                    __nv_bfloat16* __restrict__ lo)
{
    size_t i = ((size_t)blockIdx.x * 256 + threadIdx.x) * 4;
    float4 v = *(const float4*)&src[i];
    float vv[4] = {v.x, v.y, v.z, v.w};
    unsigned short hs[4], ls[4];
#pragma unroll
    for (int j = 0; j < 4; j++) {
        __nv_bfloat16 h = __float2bfloat16(vv[j]);
        __nv_bfloat16 l = __float2bfloat16(vv[j] - __bfloat162float(h));
        hs[j] = __bfloat16_as_ushort(h);
        ls[j] = __bfloat16_as_ushort(l);
    }
    uint2 ho, lo2;
    ho.x  = hs[0] | ((uint32_t)hs[1] << 16); ho.y  = hs[2] | ((uint32_t)hs[3] << 16);
    lo2.x = ls[0] | ((uint32_t)ls[1] << 16); lo2.y = ls[2] | ((uint32_t)ls[3] << 16);
    *(uint2*)&hi[i] = ho;
    *(uint2*)&lo[i] = lo2;
}

// ---------------- HMMA bf16x3 GEMM: C[M,N] = A[M,K] @ W[N,K]^T + bias ----------
// CTA 128x128, 8 warps (4x2), warp tile 32x64, m16n8k16, BK=32, 2-stage cp.async.
// 3 precision segments: AhBh + AlBh + AhBl accumulated in fp32.
__global__ __launch_bounds__(256, 2) void gemm_mma_kernel(
    const __nv_bfloat16* __restrict__ Ah, const __nv_bfloat16* __restrict__ Al,
    const __nv_bfloat16* __restrict__ Bh, const __nv_bfloat16* __restrict__ Bl,
    const float* __restrict__ bias, float* __restrict__ C,
    int M, int N, int K, int act)
{
    __shared__ __align__(16) char smc[32768];   // A: 2x8KB @0, B: 2x8KB @16384
    uint32_t sbase = smem_u32(smc);

    int t = threadIdx.x;
    int lane = t & 31, wid = t >> 5;
    int warp_m = wid & 3, warp_n = wid >> 2;
    int m0 = blockIdx.y * 128;
    int n0 = blockIdx.x * 128;

    // ---- loader mapping: per stage, 512 chunks(16B) for A + 512 for B; 2 each/thread
    uint32_t aOff[2], bOff[2];
    size_t   aG[2], bG[2];          // element offsets into A/B (excluding k)
#pragma unroll
    for (int i = 0; i < 2; i++) {
        int idx = t + i * 256;
        int row = idx >> 2, ch = idx & 3;
        uint32_t swz = (uint32_t)(ch ^ ((row >> 1) & 3));
        aOff[i] = (uint32_t)(row * 64) + swz * 16;
        bOff[i] = aOff[i];
        aG[i] = (size_t)(m0 + row) * K + ch * 8;
        bG[i] = (size_t)(n0 + row) * K + ch * 8;
    }

    // ---- ldmatrix address components (row-dependent, kstep-independent)
    uint32_t aRow64[2]; int aRswz[2];
#pragma unroll
    for (int ti = 0; ti < 2; ti++) {
        int row = warp_m * 32 + ti * 16 + (lane & 15);
        aRow64[ti] = (uint32_t)(row * 64);
        aRswz[ti] = (row >> 1) & 3;
    }
    int aChunkBase = lane >> 4;             // + kstep*2
    uint32_t bRow64[4]; int bRswz[4];
#pragma unroll
    for (int j2 = 0; j2 < 4; j2++) {
        int row = warp_n * 64 + j2 * 16 + ((lane >> 4) << 3) + (lane & 7);
        bRow64[j2] = (uint32_t)(row * 64);
        bRswz[j2] = (row >> 1) & 3;
    }
    int bChunkBase = (lane >> 3) & 1;       // + kstep*2

    float acc[2][8][4];
#pragma unroll
    for (int mi = 0; mi < 2; mi++)
#pragma unroll
        for (int nj = 0; nj < 8; nj++)
#pragma unroll
            for (int r = 0; r < 4; r++) acc[mi][nj][r] = 0.f;

    const __nv_bfloat16* Aseg[3] = {Ah, Al, Ah};
    const __nv_bfloat16* Bseg[3] = {Bh, Bh, Bl};
    int KC = K >> 5;            // 32-wide chunks per segment
    int NC = 3 * KC;

    // ---- prologue: chunk 0 -> stage 0
    {
        const __nv_bfloat16* Ap = Aseg[0];
        const __nv_bfloat16* Bp = Bseg[0];
#pragma unroll
        for (int i = 0; i < 2; i++) cp16(sbase + aOff[i], Ap + aG[i]);
#pragma unroll
        for (int i = 0; i < 2; i++) cp16(sbase + 16384 + bOff[i], Bp + bG[i]);
        cp_commit();
        cp_wait0();
    }
    __syncthreads();

    for (int c = 0; c < NC; c++) {
        int cur = c & 1, nxt = cur ^ 1;
        bool more = (c + 1) < NC;

        if (more) {
            int cn = c + 1;
            int seg = (cn >= 2 * KC) ? 2 : (cn >= KC ? 1 : 0);
            size_t ko = (size_t)(cn - seg * KC) * 32;
            const __nv_bfloat16* Ap = Aseg[seg];
            const __nv_bfloat16* Bp = Bseg[seg];
            uint32_t sa = sbase + (uint32_t)nxt * 8192;
            uint32_t sb = sbase + 16384 + (uint32_t)nxt * 8192;
#pragma unroll
            for (int i = 0; i < 2; i++) cp16(sa + aOff[i], Ap + aG[i] + ko);
#pragma unroll
            for (int i = 0; i < 2; i++) cp16(sb + bOff[i], Bp + bG[i] + ko);
            cp_commit();
        }

        uint32_t sa = sbase + (uint32_t)cur * 8192;
        uint32_t sb = sbase + 16384 + (uint32_t)cur * 8192;
#pragma unroll
        for (int kstep = 0; kstep < 2; kstep++) {
            uint32_t a[2][4], b[4][4];
#pragma unroll
            for (int ti = 0; ti < 2; ti++) {
                int ch = kstep * 2 + aChunkBase;
                uint32_t addr = sa + aRow64[ti] + (uint32_t)((ch ^ aRswz[ti]) * 16);
                ldm_x4(addr, a[ti][0], a[ti][1], a[ti][2], a[ti][3]);
            }
#pragma unroll
            for (int j2 = 0; j2 < 4; j2++) {
                int ch = kstep * 2 + bChunkBase;
                uint32_t addr = sb + bRow64[j2] + (uint32_t)((ch ^ bRswz[j2]) * 16);
                ldm_x4(addr, b[j2][0], b[j2][1], b[j2][2], b[j2][3]);
            }
#pragma unroll
            for (int mi = 0; mi < 2; mi++)
#pragma unroll
                for (int nj = 0; nj < 8; nj++)
                    mma16816(acc[mi][nj], a[mi], &b[nj >> 1][(nj & 1) * 2]);
        }

        if (more) cp_wait0();
        __syncthreads();
    }

    // ---- epilogue
    int tq = lane >> 2, tr = lane & 3;
#pragma unroll
    for (int mi = 0; mi < 2; mi++) {
#pragma unroll
        for (int nj = 0; nj < 8; nj++) {
            int row0 = m0 + warp_m * 32 + mi * 16 + tq;
            int col = n0 + warp_n * 64 + nj * 8 + tr * 2;
            float b0 = __ldg(&bias[col]), b1 = __ldg(&bias[col + 1]);
            float v0 = acc[mi][nj][0] + b0, v1 = acc[mi][nj][1] + b1;
            float v2 = acc[mi][nj][2] + b0, v3 = acc[mi][nj][3] + b1;
            if (act) {
                v0 = 0.5f * v0 * (1.0f + erff(v0 * 0.70710678118654752f));
                v1 = 0.5f * v1 * (1.0f + erff(v1 * 0.70710678118654752f));
                v2 = 0.5f * v2 * (1.0f + erff(v2 * 0.70710678118654752f));
                v3 = 0.5f * v3 * (1.0f + erff(v3 * 0.70710678118654752f));
            }
            *(float2*)&C[(size_t)row0 * N + col] = make_float2(v0, v1);
            *(float2*)&C[(size_t)(row0 + 8) * N + col] = make_float2(v2, v3);
        }
    }
}

// ---------------- RoPE on raw x -> qk_in -------------------------------------
__global__ __launch_bounds__(256) void rope_kernel(const float* __restrict__ x,
                                                   float* __restrict__ out)
{
    int tok = blockIdx.x;
    float pos = (float)(tok & (SS - 1));
    int base = tok * E_ + threadIdx.x * 4;
    int d = (threadIdx.x * 4) & (HD - 1);
    const float* xp = &x[base];
    float4 xv = *(const float4*)xp;
    float res[4];
    const float LOG2_10000 = 13.287712379549449f;
#pragma unroll
    for (int i = 0; i < 4; i++) {
        int dd = d + i;
        int j = (dd < 32) ? dd : dd - 32;
        float fr = exp2f(-(float)j * (2.0f / 64.0f) * LOG2_10000);
        float ang = pos * fr;
        float s, c;
        sincosf(ang, &s, &c);
        float v = ((const float*)&xv)[i];
        float other = (dd < 32) ? -xp[i + 32] : xp[i - 32];
        res[i] = v * c + other * s;
    }
    *(float4*)&out[base] = make_float4(res[0], res[1], res[2], res[3]);
}

// ---------------- sliding-window attention (flash-style, online softmax) -----
__global__ __launch_bounds__(256) void attn_kernel(
    const float* __restrict__ q, const float* __restrict__ k,
    const float* __restrict__ v, float* __restrict__ out)
{
    extern __shared__ float sm[];
    float* q_s = sm;
    float* k_s = q_s + 64 * SP;
    float* v_s = k_s + 64 * SP;
    float* p_s = v_s + 64 * SP;

    int b = blockIdx.z, h = blockIdx.y;
    int q0 = blockIdx.x * 64;
    int t = threadIdx.x;
    int tq = t >> 4, tk = t & 15;

#pragma unroll
    for (int i = 0; i < 4; i++) {
        int l = t + i * 256;
        int r = l >> 4;
        int c = (l & 15) * 4;
        *(float4*)&q_s[r * SP + c] =
            *(const float4*)&q[((size_t)(b * SS + q0 + r)) * E_ + h * HD + c];
    }

    float m[4], lsum[4], acc[4][4];
#pragma unroll
    for (int i = 0; i < 4; i++) {
        m[i] = -1e30f; lsum[i] = 0.f;
#pragma unroll
        for (int j = 0; j < 4; j++) acc[i][j] = 0.f;
    }

    int kstart = q0 - WIN; if (kstart < 0) kstart = 0;
    int kend = q0 + 64 + WIN; if (kend > SS) kend = SS;
    const float scale = 0.125f;

    for (int kb = kstart; kb < kend; kb += 64) {
        __syncthreads();
#pragma unroll
        for (int i = 0; i < 4; i++) {
            int l = t + i * 256;
            int r = l >> 4;
            int c = (l & 15) * 4;
            size_t gi = ((size_t)(b * SS + kb + r)) * E_ + h * HD + c;
            *(float4*)&k_s[r * SP + c] = *(const float4*)&k[gi];
            *(float4*)&v_s[r * SP + c] = *(const float4*)&v[gi];
        }
        __syncthreads();

        float s[4][4];
#pragma unroll
        for (int i = 0; i < 4; i++)
#pragma unroll
            for (int j = 0; j < 4; j++) s[i][j] = 0.f;
#pragma unroll
        for (int d4 = 0; d4 < 16; d4++) {
            float4 qv[4], kv[4];
#pragma unroll
            for (int i = 0; i < 4; i++)
                qv[i] = *(const float4*)&q_s[(tq * 4 + i) * SP + d4 * 4];
#pragma unroll
            for (int j = 0; j < 4; j++)
                kv[j] = *(const float4*)&k_s[(tk * 4 + j) * SP + d4 * 4];
#pragma unroll
            for (int i = 0; i < 4; i++)
#pragma unroll
                for (int j = 0; j < 4; j++)
                    s[i][j] += qv[i].x * kv[j].x + qv[i].y * kv[j].y +
                               qv[i].z * kv[j].z + qv[i].w * kv[j].w;
        }

#pragma unroll
        for (int i = 0; i < 4; i++) {
            int qi = q0 + tq * 4 + i;
            float rmax = -1e30f;
#pragma unroll
            for (int j = 0; j < 4; j++) {
                int diff = qi - (kb + tk * 4 + j);
                bool ok = (diff <= WIN) && (diff >= -WIN);
                s[i][j] = ok ? s[i][j] * scale : -1e30f;
                rmax = fmaxf(rmax, s[i][j]);
            }
            rmax = fmaxf(rmax, __shfl_xor_sync(0xffffffffu, rmax, 1));
            rmax = fmaxf(rmax, __shfl_xor_sync(0xffffffffu, rmax, 2));
            rmax = fmaxf(rmax, __shfl_xor_sync(0xffffffffu, rmax, 4));
            rmax = fmaxf(rmax, __shfl_xor_sync(0xffffffffu, rmax, 8));
            float mnew = fmaxf(m[i], rmax);
            float corr = expf(m[i] - mnew);
            float rsum = 0.f;
#pragma unroll
            for (int j = 0; j < 4; j++) {
                float p = (s[i][j] > -1e29f) ? expf(s[i][j] - mnew) : 0.f;
                p_s[(tq * 4 + i) * SP + tk * 4 + j] = p;
                rsum += p;
            }
            rsum += __shfl_xor_sync(0xffffffffu, rsum, 1);
            rsum += __shfl_xor_sync(0xffffffffu, rsum, 2);
            rsum += __shfl_xor_sync(0xffffffffu, rsum, 4);
            rsum += __shfl_xor_sync(0xffffffffu, rsum, 8);
            m[i] = mnew;
            lsum[i] = lsum[i] * corr + rsum;
#pragma unroll
            for (int j = 0; j < 4; j++) acc[i][j] *= corr;
        }
        __syncthreads();

#pragma unroll 4
        for (int kk = 0; kk < 64; kk++) {
            float4 vv = *(const float4*)&v_s[kk * SP + tk * 4];
#pragma unroll
            for (int i = 0; i < 4; i++) {
                float p = p_s[(tq * 4 + i) * SP + kk];
                acc[i][0] += p * vv.x; acc[i][1] += p * vv.y;
                acc[i][2] += p * vv.z; acc[i][3] += p * vv.w;
            }
        }
    }

#pragma unroll
    for (int i = 0; i < 4; i++) {
        float inv = 1.f / lsum[i];
        size_t o = ((size_t)(b * SS + q0 + tq * 4 + i)) * E_ + h * HD + tk * 4;
        *(float4*)&out[o] = make_float4(acc[i][0] * inv, acc[i][1] * inv,
                                        acc[i][2] * inv, acc[i][3] * inv);
    }
}

// ---------------- residual add + LayerNorm ------------------------------------
__global__ __launch_bounds__(256) void add_ln_kernel(
    const float* __restrict__ a, const float* __restrict__ r,
    const float* __restrict__ g, const float* __restrict__ be,
    float* __restrict__ out)
{
    int row = blockIdx.x;
    int t = threadIdx.x;
    size_t base = (size_t)row * E_;
    float4 av = *(const float4*)&a[base + t * 4];
    float4 rv = *(const float4*)&r[base + t * 4];
    float v0 = av.x + rv.x, v1 = av.y + rv.y, v2 = av.z + rv.z, v3 = av.w + rv.w;
    float sum = v0 + v1 + v2 + v3;
    float sq = v0 * v0 + v1 * v1 + v2 * v2 + v3 * v3;
#pragma unroll
    for (int off = 16; off; off >>= 1) {
        sum += __shfl_xor_sync(0xffffffffu, sum, off);
        sq  += __shfl_xor_sync(0xffffffffu, sq, off);
    }
    __shared__ float ss[8], sq2[8], stat[2];
    int w = t >> 5;
    if ((t & 31) == 0) { ss[w] = sum; sq2[w] = sq; }
    __syncthreads();
    if (t == 0) {
        float S1 = 0.f, S2 = 0.f;
        for (int i = 0; i < 8; i++) { S1 += ss[i]; S2 += sq2[i]; }
        float mean = S1 * (1.0f / E_);
        float var = S2 * (1.0f / E_) - mean * mean;
        stat[0] = mean;
        stat[1] = rsqrtf(var + 1e-5f);
    }
    __syncthreads();
    float mean = stat[0], rstd = stat[1];
    float4 gv = *(const float4*)&g[t * 4];
    float4 bv = *(const float4*)&be[t * 4];
    float4 o;
    o.x = (v0 - mean) * rstd * gv.x + bv.x;
    o.y = (v1 - mean) * rstd * gv.y + bv.y;
    o.z = (v2 - mean) * rstd * gv.z + bv.z;
    o.w = (v3 - mean) * rstd * gv.w + bv.w;
    *(float4*)&out[base + t * 4] = o;
}

// ---------------- launch -------------------------------------------------------
extern "C" void kernel_launch(void* const* d_in, const int* in_sizes, int n_in,
                              void* d_out, int out_size)
{
    (void)in_sizes; (void)n_in; (void)out_size;
    const float* x    = (const float*)d_in[0];
    const float* ipw  = (const float*)d_in[1];
    const float* ipb  = (const float*)d_in[2];
    const float* opw  = (const float*)d_in[3];
    const float* opb  = (const float*)d_in[4];
    const float* ln1g = (const float*)d_in[5];
    const float* ln1b = (const float*)d_in[6];
    const float* w1   = (const float*)d_in[7];
    const float* b1   = (const float*)d_in[8];
    const float* w2   = (const float*)d_in[9];
    const float* b2   = (const float*)d_in[10];
    const float* ln2g = (const float*)d_in[11];
    const float* ln2b = (const float*)d_in[12];
    float* out = (float*)d_out;

    float *qkin, *qb, *kb, *vb, *ctx, *tmp, *x1, *hid;
    cudaGetSymbolAddress((void**)&qkin, g_qkin);
    cudaGetSymbolAddress((void**)&qb,   g_q);
    cudaGetSymbolAddress((void**)&kb,   g_k);
    cudaGetSymbolAddress((void**)&vb,   g_v);
    cudaGetSymbolAddress((void**)&ctx,  g_ctx);
    cudaGetSymbolAddress((void**)&tmp,  g_tmp);
    cudaGetSymbolAddress((void**)&x1,   g_x1);
    cudaGetSymbolAddress((void**)&hid,  g_hid);

    __nv_bfloat16 *a1h, *a1l, *a2h, *a2l, *hh, *hl;
    __nv_bfloat16 *wih, *wil, *woh, *wol, *w1h, *w1l, *w2h, *w2l;
    cudaGetSymbolAddress((void**)&a1h, g_a1h); cudaGetSymbolAddress((void**)&a1l, g_a1l);
    cudaGetSymbolAddress((void**)&a2h, g_a2h); cudaGetSymbolAddress((void**)&a2l, g_a2l);
    cudaGetSymbolAddress((void**)&hh,  g_hh);  cudaGetSymbolAddress((void**)&hl,  g_hl);
    cudaGetSymbolAddress((void**)&wih, g_wih); cudaGetSymbolAddress((void**)&wil, g_wil);
    cudaGetSymbolAddress((void**)&woh, g_woh); cudaGetSymbolAddress((void**)&wol, g_wol);
    cudaGetSymbolAddress((void**)&w1h, g_w1h); cudaGetSymbolAddress((void**)&w1l, g_w1l);
    cudaGetSymbolAddress((void**)&w2h, g_w2h); cudaGetSymbolAddress((void**)&w2l, g_w2l);

    int attn_smem = 4 * 64 * SP * (int)sizeof(float);
    cudaFuncSetAttribute(attn_kernel,
                         cudaFuncAttributeMaxDynamicSharedMemorySize, attn_smem);

    // 1) RoPE(x) -> qk_in ; splits of activations + weights
    rope_kernel<<<BS, 256>>>(x, qkin);
    split_kernel<<<(BS * E_) / 1024, 256>>>(qkin, a1h, a1l);
    split_kernel<<<(BS * E_) / 1024, 256>>>(x, a2h, a2l);
    split_kernel<<<(3 * E_ * E_) / 1024, 256>>>(ipw, wih, wil);
    split_kernel<<<(E_ * E_) / 1024, 256>>>(opw, woh, wol);
    split_kernel<<<(FF * E_) / 1024, 256>>>(w1, w1h, w1l);
    split_kernel<<<(FF * E_) / 1024, 256>>>(w2, w2h, w2l);

    // 2) Q, K from roped input; V from raw x
    dim3 gE(E_ / 128, BS / 128);
    gemm_mma_kernel<<<gE, 256>>>(a1h, a1l, wih, wil, ipb, qb, BS, E_, E_, 0);
    gemm_mma_kernel<<<gE, 256>>>(a1h, a1l, wih + (size_t)E_*E_, wil + (size_t)E_*E_,
                                 ipb + E_, kb, BS, E_, E_, 0);
    gemm_mma_kernel<<<gE, 256>>>(a2h, a2l, wih + (size_t)2*E_*E_, wil + (size_t)2*E_*E_,
                                 ipb + 2 * E_, vb, BS, E_, E_, 0);

    // 3) sliding-window attention -> ctx
    attn_kernel<<<dim3(SS / 64, NH, BB), 256, attn_smem>>>(qb, kb, vb, ctx);

    // 4) out-proj, residual + LN1 -> x1
    split_kernel<<<(BS * E_) / 1024, 256>>>(ctx, a2h, a2l);
    gemm_mma_kernel<<<gE, 256>>>(a2h, a2l, woh, wol, opb, tmp, BS, E_, E_, 0);
    add_ln_kernel<<<BS, 256>>>(x, tmp, ln1g, ln1b, x1);

    // 5) FFN
    split_kernel<<<(BS * E_) / 1024, 256>>>(x1, a1h, a1l);
    gemm_mma_kernel<<<dim3(FF / 128, BS / 128), 256>>>(a1h, a1l, w1h, w1l, b1,
                                                       hid, BS, FF, E_, 1);
    split_kernel<<<(int)(((size_t)BS * FF) / 1024), 256>>>(hid, hh, hl);
    gemm_mma_kernel<<<gE, 256>>>(hh, hl, w2h, w2l, b2, tmp, BS, E_, FF, 0);
    add_ln_kernel<<<BS, 256>>>(x1, tmp, ln2g, ln2b, out);
}

// round 5
// speedup vs baseline: 2.1412x; 1.0707x over previous
#include <cuda_runtime.h>
#include <cuda_bf16.h>
#include <math.h>
#include <stdint.h>

#define E_   1024
#define NH   16
#define HD   64
#define WIN  256
#define BB   8
#define SS   1024
#define BS   (BB*SS)
#define FF   4096
#define SP   68   // padded smem row stride (floats) for attention tiles

// ---------------- scratch ------------------------------------------------------
__device__ float g_v[BS*E_];
__device__ float g_tmp[BS*E_];
__device__ float g_x1[BS*E_];
__device__ float g_qk[(size_t)BS*2*E_];          // fused Q|K output

__device__ __nv_bfloat16 g_a1h[BS*E_], g_a1l[BS*E_];
__device__ __nv_bfloat16 g_a2h[BS*E_], g_a2l[BS*E_];
__device__ __nv_bfloat16 g_hh[(size_t)BS*FF], g_hl[(size_t)BS*FF];
__device__ __nv_bfloat16 g_wih[3*E_*E_], g_wil[3*E_*E_];
__device__ __nv_bfloat16 g_woh[E_*E_],   g_wol[E_*E_];
__device__ __nv_bfloat16 g_w1h[FF*E_],   g_w1l[FF*E_];
__device__ __nv_bfloat16 g_w2h[FF*E_],   g_w2l[FF*E_];

// ---------------- helpers -------------------------------------------------------
__device__ __forceinline__ uint32_t smem_u32(const void* p) {
    uint32_t a;
    asm("{ .reg .u64 t; cvta.to.shared.u64 t, %1; cvt.u32.u64 %0, t; }" : "=r"(a) : "l"(p));
    return a;
}
__device__ __forceinline__ void cp16(uint32_t dst, const void* src) {
    asm volatile("cp.async.cg.shared.global [%0], [%1], 16;" :: "r"(dst), "l"(src));
}
__device__ __forceinline__ void cp_commit() { asm volatile("cp.async.commit_group;"); }
__device__ __forceinline__ void cp_wait2()  { asm volatile("cp.async.wait_group 2;" ::: "memory"); }
__device__ __forceinline__ void ldm_x4(uint32_t addr, uint32_t& r0, uint32_t& r1,
                                       uint32_t& r2, uint32_t& r3) {
    asm volatile("ldmatrix.sync.aligned.m8n8.x4.shared.b16 {%0,%1,%2,%3}, [%4];"
                 : "=r"(r0), "=r"(r1), "=r"(r2), "=r"(r3) : "r"(addr));
}
__device__ __forceinline__ void mma16816(float* c, const uint32_t* a, const uint32_t* b) {
    asm volatile(
        "mma.sync.aligned.m16n8k16.row.col.f32.bf16.bf16.f32 "
        "{%0,%1,%2,%3}, {%4,%5,%6,%7}, {%8,%9}, {%0,%1,%2,%3};"
        : "+f"(c[0]), "+f"(c[1]), "+f"(c[2]), "+f"(c[3])
        : "r"(a[0]), "r"(a[1]), "r"(a[2]), "r"(a[3]), "r"(b[0]), "r"(b[1]));
}
__device__ __forceinline__ void split1(float v, unsigned short& h, unsigned short& l) {
    __nv_bfloat16 hb = __float2bfloat16(v);
    __nv_bfloat16 lb = __float2bfloat16(v - __bfloat162float(hb));
    h = __bfloat16_as_ushort(hb);
    l = __bfloat16_as_ushort(lb);
}

// ---------------- split fp32 -> bf16 hi/lo --------------------------------------
__global__ __launch_bounds__(256) void split_kernel(const float* __restrict__ src,
                                                    __nv_bfloat16* __restrict__ hi,
                                                    __nv_bfloat16* __restrict__ lo)
{
    size_t i = ((size_t)blockIdx.x * 256 + threadIdx.x) * 4;
    float4 v = *(const float4*)&src[i];
    float vv[4] = {v.x, v.y, v.z, v.w};
    unsigned short hs[4], ls[4];
#pragma unroll
    for (int j = 0; j < 4; j++) split1(vv[j], hs[j], ls[j]);
    uint2 ho, lo2;
    ho.x  = hs[0] | ((uint32_t)hs[1] << 16); ho.y  = hs[2] | ((uint32_t)hs[3] << 16);
    lo2.x = ls[0] | ((uint32_t)ls[1] << 16); lo2.y = ls[2] | ((uint32_t)ls[3] << 16);
    *(uint2*)&hi[i] = ho;
    *(uint2*)&lo[i] = lo2;
}

// ---------------- RoPE on raw x -> bf16 hi/lo ------------------------------------
__global__ __launch_bounds__(256) void rope_split_kernel(const float* __restrict__ x,
                                                         __nv_bfloat16* __restrict__ hi,
                                                         __nv_bfloat16* __restrict__ lo)
{
    int tok = blockIdx.x;
    float pos = (float)(tok & (SS - 1));
    int base = tok * E_ + threadIdx.x * 4;
    int d = (threadIdx.x * 4) & (HD - 1);
    const float* xp = &x[base];
    float4 xv = *(const float4*)xp;
    float res[4];
    const float LOG2_10000 = 13.287712379549449f;
#pragma unroll
    for (int i = 0; i < 4; i++) {
        int dd = d + i;
        int j = (dd < 32) ? dd : dd - 32;
        float fr = exp2f(-(float)j * (2.0f / 64.0f) * LOG2_10000);
        float ang = pos * fr;
        float s, c;
        sincosf(ang, &s, &c);
        float v = ((const float*)&xv)[i];
        float other = (dd < 32) ? -xp[i + 32] : xp[i - 32];
        res[i] = v * c + other * s;
    }
    unsigned short hs[4], ls[4];
#pragma unroll
    for (int j = 0; j < 4; j++) split1(res[j], hs[j], ls[j]);
    uint2 ho, lo2;
    ho.x  = hs[0] | ((uint32_t)hs[1] << 16); ho.y  = hs[2] | ((uint32_t)hs[3] << 16);
    lo2.x = ls[0] | ((uint32_t)ls[1] << 16); lo2.y = ls[2] | ((uint32_t)ls[3] << 16);
    *(uint2*)&hi[base] = ho;
    *(uint2*)&lo[base] = lo2;
}

// ---------------- HMMA bf16x3 GEMM: C[M,N] = A[M,K] @ W[N,K]^T + bias -----------
// CTA 128x128, 8 warps (4x2), m16n8k16, BK=32, 4-stage cp.async pipeline.
// MODE 0: fp32 C out.  MODE 1: bf16 hi/lo out (fused split).  ACT 1: exact GELU.
#define STG 4
#define GEMM_SMEM (STG * 16384)

template<int ACT, int MODE>
__global__ __launch_bounds__(256, 2) void gemm_mma_kernel(
    const __nv_bfloat16* __restrict__ Ah, const __nv_bfloat16* __restrict__ Al,
    const __nv_bfloat16* __restrict__ Bh, const __nv_bfloat16* __restrict__ Bl,
    const float* __restrict__ bias, float* __restrict__ C,
    __nv_bfloat16* __restrict__ Ch, __nv_bfloat16* __restrict__ Cl,
    int M, int N, int K)
{
    extern __shared__ __align__(16) char smc[];   // A: STGx8KB @0, B: STGx8KB @STG*8192
    uint32_t sbase = smem_u32(smc);
    const uint32_t BOFF = STG * 8192;

    int t = threadIdx.x;
    int lane = t & 31, wid = t >> 5;
    int warp_m = wid & 3, warp_n = wid >> 2;
    int m0 = blockIdx.y * 128;
    int n0 = blockIdx.x * 128;

    // loader mapping (2 x 16B chunks per thread per matrix per stage)
    uint32_t aOff[2];
    size_t   aG[2], bG[2];
#pragma unroll
    for (int i = 0; i < 2; i++) {
        int idx = t + i * 256;
        int row = idx >> 2, ch = idx & 3;
        uint32_t swz = (uint32_t)(ch ^ ((row >> 1) & 3));
        aOff[i] = (uint32_t)(row * 64) + swz * 16;
        aG[i] = (size_t)(m0 + row) * K + ch * 8;
        bG[i] = (size_t)(n0 + row) * K + ch * 8;
    }

    // ldmatrix address components
    uint32_t aRow64[2]; int aRswz[2];
#pragma unroll
    for (int ti = 0; ti < 2; ti++) {
        int row = warp_m * 32 + ti * 16 + (lane & 15);
        aRow64[ti] = (uint32_t)(row * 64);
        aRswz[ti] = (row >> 1) & 3;
    }
    int aChunkBase = lane >> 4;
    uint32_t bRow64[4]; int bRswz[4];
#pragma unroll
    for (int j2 = 0; j2 < 4; j2++) {
        int row = warp_n * 64 + j2 * 16 + ((lane >> 4) << 3) + (lane & 7);
        bRow64[j2] = (uint32_t)(row * 64);
        bRswz[j2] = (row >> 1) & 3;
    }
    int bChunkBase = (lane >> 3) & 1;

    float acc[2][8][4];
#pragma unroll
    for (int mi = 0; mi < 2; mi++)
#pragma unroll
        for (int nj = 0; nj < 8; nj++)
#pragma unroll
            for (int r = 0; r < 4; r++) acc[mi][nj][r] = 0.f;

    const __nv_bfloat16* Aseg[3] = {Ah, Al, Ah};
    const __nv_bfloat16* Bseg[3] = {Bh, Bh, Bl};
    int KC = K >> 5;
    int NC = 3 * KC;

    // prologue: chunks 0..2 -> stages 0..2 (one commit group each)
#pragma unroll
    for (int p = 0; p < 3; p++) {
        int seg = (p >= 2 * KC) ? 2 : (p >= KC ? 1 : 0);
        size_t ko = (size_t)(p - seg * KC) * 32;
        const __nv_bfloat16* Ap = Aseg[seg];
        const __nv_bfloat16* Bp = Bseg[seg];
        uint32_t sa = sbase + (uint32_t)p * 8192;
        uint32_t sb = sbase + BOFF + (uint32_t)p * 8192;
#pragma unroll
        for (int i = 0; i < 2; i++) cp16(sa + aOff[i], Ap + aG[i] + ko);
#pragma unroll
        for (int i = 0; i < 2; i++) cp16(sb + aOff[i], Bp + bG[i] + ko);
        cp_commit();
    }

    for (int c = 0; c < NC; c++) {
        cp_wait2();
        __syncthreads();

        // issue loads for chunk c+3 (always commit a group to keep accounting)
        if (c + 3 < NC) {
            int cn = c + 3;
            int seg = (cn >= 2 * KC) ? 2 : (cn >= KC ? 1 : 0);
            size_t ko = (size_t)(cn - seg * KC) * 32;
            const __nv_bfloat16* Ap = Aseg[seg];
            const __nv_bfloat16* Bp = Bseg[seg];
            uint32_t st = (uint32_t)(cn & (STG - 1));
            uint32_t sa = sbase + st * 8192;
            uint32_t sb = sbase + BOFF + st * 8192;
#pragma unroll
            for (int i = 0; i < 2; i++) cp16(sa + aOff[i], Ap + aG[i] + ko);
#pragma unroll
            for (int i = 0; i < 2; i++) cp16(sb + aOff[i], Bp + bG[i] + ko);
        }
        cp_commit();

        uint32_t sa = sbase + (uint32_t)(c & (STG - 1)) * 8192;
        uint32_t sb = sbase + BOFF + (uint32_t)(c & (STG - 1)) * 8192;
#pragma unroll
        for (int kstep = 0; kstep < 2; kstep++) {
            uint32_t a[2][4], b[4][4];
#pragma unroll
            for (int ti = 0; ti < 2; ti++) {
                int ch = kstep * 2 + aChunkBase;
                uint32_t addr = sa + aRow64[ti] + (uint32_t)((ch ^ aRswz[ti]) * 16);
                ldm_x4(addr, a[ti][0], a[ti][1], a[ti][2], a[ti][3]);
            }
#pragma unroll
            for (int j2 = 0; j2 < 4; j2++) {
                int ch = kstep * 2 + bChunkBase;
                uint32_t addr = sb + bRow64[j2] + (uint32_t)((ch ^ bRswz[j2]) * 16);
                ldm_x4(addr, b[j2][0], b[j2][1], b[j2][2], b[j2][3]);
            }
#pragma unroll
            for (int mi = 0; mi < 2; mi++)
#pragma unroll
                for (int nj = 0; nj < 8; nj++)
                    mma16816(acc[mi][nj], a[mi], &b[nj >> 1][(nj & 1) * 2]);
        }
    }

    // ---- epilogue
    int tq = lane >> 2, tr = lane & 3;
#pragma unroll
    for (int mi = 0; mi < 2; mi++) {
#pragma unroll
        for (int nj = 0; nj < 8; nj++) {
            int row0 = m0 + warp_m * 32 + mi * 16 + tq;
            int col = n0 + warp_n * 64 + nj * 8 + tr * 2;
            float b0 = __ldg(&bias[col]), b1 = __ldg(&bias[col + 1]);
            float v0 = acc[mi][nj][0] + b0, v1 = acc[mi][nj][1] + b1;
            float v2 = acc[mi][nj][2] + b0, v3 = acc[mi][nj][3] + b1;
            if (ACT) {
                v0 = 0.5f * v0 * (1.0f + erff(v0 * 0.70710678118654752f));
                v1 = 0.5f * v1 * (1.0f + erff(v1 * 0.70710678118654752f));
                v2 = 0.5f * v2 * (1.0f + erff(v2 * 0.70710678118654752f));
                v3 = 0.5f * v3 * (1.0f + erff(v3 * 0.70710678118654752f));
            }
            if (MODE == 0) {
                *(float2*)&C[(size_t)row0 * N + col] = make_float2(v0, v1);
                *(float2*)&C[(size_t)(row0 + 8) * N + col] = make_float2(v2, v3);
            } else {
                unsigned short h0, l0, h1, l1, h2, l2, h3, l3;
                split1(v0, h0, l0); split1(v1, h1, l1);
                split1(v2, h2, l2); split1(v3, h3, l3);
                *(uint32_t*)&Ch[(size_t)row0 * N + col] = h0 | ((uint32_t)h1 << 16);
                *(uint32_t*)&Cl[(size_t)row0 * N + col] = l0 | ((uint32_t)l1 << 16);
                *(uint32_t*)&Ch[(size_t)(row0 + 8) * N + col] = h2 | ((uint32_t)h3 << 16);
                *(uint32_t*)&Cl[(size_t)(row0 + 8) * N + col] = l2 | ((uint32_t)l3 << 16);
            }
        }
    }
}

// ---------------- sliding-window attention -> bf16 hi/lo ctx --------------------
__global__ __launch_bounds__(256) void attn_kernel(
    const float* __restrict__ q, const float* __restrict__ k,
    const float* __restrict__ v, int qks,
    __nv_bfloat16* __restrict__ ch, __nv_bfloat16* __restrict__ cl)
{
    extern __shared__ float sm[];
    float* q_s = sm;
    float* k_s = q_s + 64 * SP;
    float* v_s = k_s + 64 * SP;
    float* p_s = v_s + 64 * SP;

    int b = blockIdx.z, h = blockIdx.y;
    int q0 = blockIdx.x * 64;
    int t = threadIdx.x;
    int tq = t >> 4, tk = t & 15;

#pragma unroll
    for (int i = 0; i < 4; i++) {
        int l = t + i * 256;
        int r = l >> 4;
        int c = (l & 15) * 4;
        *(float4*)&q_s[r * SP + c] =
            *(const float4*)&q[((size_t)(b * SS + q0 + r)) * qks + h * HD + c];
    }

    float m[4], lsum[4], acc[4][4];
#pragma unroll
    for (int i = 0; i < 4; i++) {
        m[i] = -1e30f; lsum[i] = 0.f;
#pragma unroll
        for (int j = 0; j < 4; j++) acc[i][j] = 0.f;
    }

    int kstart = q0 - WIN; if (kstart < 0) kstart = 0;
    int kend = q0 + 64 + WIN; if (kend > SS) kend = SS;
    const float scale = 0.125f;

    for (int kb = kstart; kb < kend; kb += 64) {
        __syncthreads();
#pragma unroll
        for (int i = 0; i < 4; i++) {
            int l = t + i * 256;
            int r = l >> 4;
            int c = (l & 15) * 4;
            *(float4*)&k_s[r * SP + c] =
                *(const float4*)&k[((size_t)(b * SS + kb + r)) * qks + h * HD + c];
            *(float4*)&v_s[r * SP + c] =
                *(const float4*)&v[((size_t)(b * SS + kb + r)) * E_ + h * HD + c];
        }
        __syncthreads();

        float s[4][4];
#pragma unroll
        for (int i = 0; i < 4; i++)
#pragma unroll
            for (int j = 0; j < 4; j++) s[i][j] = 0.f;
#pragma unroll
        for (int d4 = 0; d4 < 16; d4++) {
            float4 qv[4], kv[4];
#pragma unroll
            for (int i = 0; i < 4; i++)
                qv[i] = *(const float4*)&q_s[(tq * 4 + i) * SP + d4 * 4];
#pragma unroll
            for (int j = 0; j < 4; j++)
                kv[j] = *(const float4*)&k_s[(tk * 4 + j) * SP + d4 * 4];
#pragma unroll
            for (int i = 0; i < 4; i++)
#pragma unroll
                for (int j = 0; j < 4; j++)
                    s[i][j] += qv[i].x * kv[j].x + qv[i].y * kv[j].y +
                               qv[i].z * kv[j].z + qv[i].w * kv[j].w;
        }

#pragma unroll
        for (int i = 0; i < 4; i++) {
            int qi = q0 + tq * 4 + i;
            float rmax = -1e30f;
#pragma unroll
            for (int j = 0; j < 4; j++) {
                int diff = qi - (kb + tk * 4 + j);
                bool ok = (diff <= WIN) && (diff >= -WIN);
                s[i][j] = ok ? s[i][j] * scale : -1e30f;
                rmax = fmaxf(rmax, s[i][j]);
            }
            rmax = fmaxf(rmax, __shfl_xor_sync(0xffffffffu, rmax, 1));
            rmax = fmaxf(rmax, __shfl_xor_sync(0xffffffffu, rmax, 2));
            rmax = fmaxf(rmax, __shfl_xor_sync(0xffffffffu, rmax, 4));
            rmax = fmaxf(rmax, __shfl_xor_sync(0xffffffffu, rmax, 8));
            float mnew = fmaxf(m[i], rmax);
            float corr = expf(m[i] - mnew);
            float rsum = 0.f;
#pragma unroll
            for (int j = 0; j < 4; j++) {
                float p = (s[i][j] > -1e29f) ? expf(s[i][j] - mnew) : 0.f;
                p_s[(tq * 4 + i) * SP + tk * 4 + j] = p;
                rsum += p;
            }
            rsum += __shfl_xor_sync(0xffffffffu, rsum, 1);
            rsum += __shfl_xor_sync(0xffffffffu, rsum, 2);
            rsum += __shfl_xor_sync(0xffffffffu, rsum, 4);
            rsum += __shfl_xor_sync(0xffffffffu, rsum, 8);
            m[i] = mnew;
            lsum[i] = lsum[i] * corr + rsum;
#pragma unroll
            for (int j = 0; j < 4; j++) acc[i][j] *= corr;
        }
        __syncthreads();

#pragma unroll 4
        for (int kk = 0; kk < 64; kk++) {
            float4 vv = *(const float4*)&v_s[kk * SP + tk * 4];
#pragma unroll
            for (int i = 0; i < 4; i++) {
                float p = p_s[(tq * 4 + i) * SP + kk];
                acc[i][0] += p * vv.x; acc[i][1] += p * vv.y;
                acc[i][2] += p * vv.z; acc[i][3] += p * vv.w;
            }
        }
    }

#pragma unroll
    for (int i = 0; i < 4; i++) {
        float inv = 1.f / lsum[i];
        size_t o = ((size_t)(b * SS + q0 + tq * 4 + i)) * E_ + h * HD + tk * 4;
        unsigned short hs[4], ls[4];
#pragma unroll
        for (int j = 0; j < 4; j++) split1(acc[i][j] * inv, hs[j], ls[j]);
        uint2 ho, lo2;
        ho.x  = hs[0] | ((uint32_t)hs[1] << 16); ho.y  = hs[2] | ((uint32_t)hs[3] << 16);
        lo2.x = ls[0] | ((uint32_t)ls[1] << 16); lo2.y = ls[2] | ((uint32_t)ls[3] << 16);
        *(uint2*)&ch[o] = ho;
        *(uint2*)&cl[o] = lo2;
    }
}

// ---------------- residual add + LayerNorm (optional fused bf16 split) ----------
__global__ __launch_bounds__(256) void add_ln_kernel(
    const float* __restrict__ a, const float* __restrict__ r,
    const float* __restrict__ g, const float* __restrict__ be,
    float* __restrict__ out,
    __nv_bfloat16* __restrict__ oh, __nv_bfloat16* __restrict__ ol)
{
    int row = blockIdx.x;
    int t = threadIdx.x;
    size_t base = (size_t)row * E_;
    float4 av = *(const float4*)&a[base + t * 4];
    float4 rv = *(const float4*)&r[base + t * 4];
    float v0 = av.x + rv.x, v1 = av.y + rv.y, v2 = av.z + rv.z, v3 = av.w + rv.w;
    float sum = v0 + v1 + v2 + v3;
    float sq = v0 * v0 + v1 * v1 + v2 * v2 + v3 * v3;
#pragma unroll
    for (int off = 16; off; off >>= 1) {
        sum += __shfl_xor_sync(0xffffffffu, sum, off);
        sq  += __shfl_xor_sync(0xffffffffu, sq, off);
    }
    __shared__ float ss[8], sq2[8], stat[2];
    int w = t >> 5;
    if ((t & 31) == 0) { ss[w] = sum; sq2[w] = sq; }
    __syncthreads();
    if (t == 0) {
        float S1 = 0.f, S2 = 0.f;
        for (int i = 0; i < 8; i++) { S1 += ss[i]; S2 += sq2[i]; }
        float mean = S1 * (1.0f / E_);
        float var = S2 * (1.0f / E_) - mean * mean;
        stat[0] = mean;
        stat[1] = rsqrtf(var + 1e-5f);
    }
    __syncthreads();
    float mean = stat[0], rstd = stat[1];
    float4 gv = *(const float4*)&g[t * 4];
    float4 bv = *(const float4*)&be[t * 4];
    float o[4];
    o[0] = (v0 - mean) * rstd * gv.x + bv.x;
    o[1] = (v1 - mean) * rstd * gv.y + bv.y;
    o[2] = (v2 - mean) * rstd * gv.z + bv.z;
    o[3] = (v3 - mean) * rstd * gv.w + bv.w;
    *(float4*)&out[base + t * 4] = make_float4(o[0], o[1], o[2], o[3]);
    if (oh) {
        unsigned short hs[4], ls[4];
#pragma unroll
        for (int j = 0; j < 4; j++) split1(o[j], hs[j], ls[j]);
        uint2 ho, lo2;
        ho.x  = hs[0] | ((uint32_t)hs[1] << 16); ho.y  = hs[2] | ((uint32_t)hs[3] << 16);
        lo2.x = ls[0] | ((uint32_t)ls[1] << 16); lo2.y = ls[2] | ((uint32_t)ls[3] << 16);
        *(uint2*)&oh[base + t * 4] = ho;
        *(uint2*)&ol[base + t * 4] = lo2;
    }
}

// ---------------- launch ---------------------------------------------------------
extern "C" void kernel_launch(void* const* d_in, const int* in_sizes, int n_in,
                              void* d_out, int out_size)
{
    (void)in_sizes; (void)n_in; (void)out_size;
    const float* x    = (const float*)d_in[0];
    const float* ipw  = (const float*)d_in[1];
    const float* ipb  = (const float*)d_in[2];
    const float* opw  = (const float*)d_in[3];
    const float* opb  = (const float*)d_in[4];
    const float* ln1g = (const float*)d_in[5];
    const float* ln1b = (const float*)d_in[6];
    const float* w1   = (const float*)d_in[7];
    const float* b1   = (const float*)d_in[8];
    const float* w2   = (const float*)d_in[9];
    const float* b2   = (const float*)d_in[10];
    const float* ln2g = (const float*)d_in[11];
    const float* ln2b = (const float*)d_in[12];
    float* out = (float*)d_out;

    float *vb, *tmp, *x1, *qk;
    cudaGetSymbolAddress((void**)&vb,  g_v);
    cudaGetSymbolAddress((void**)&tmp, g_tmp);
    cudaGetSymbolAddress((void**)&x1,  g_x1);
    cudaGetSymbolAddress((void**)&qk,  g_qk);

    __nv_bfloat16 *a1h, *a1l, *a2h, *a2l, *hh, *hl;
    __nv_bfloat16 *wih, *wil, *woh, *wol, *w1h, *w1l, *w2h, *w2l;
    cudaGetSymbolAddress((void**)&a1h, g_a1h); cudaGetSymbolAddress((void**)&a1l, g_a1l);
    cudaGetSymbolAddress((void**)&a2h, g_a2h); cudaGetSymbolAddress((void**)&a2l, g_a2l);
    cudaGetSymbolAddress((void**)&hh,  g_hh);  cudaGetSymbolAddress((void**)&hl,  g_hl);
    cudaGetSymbolAddress((void**)&wih, g_wih); cudaGetSymbolAddress((void**)&wil, g_wil);
    cudaGetSymbolAddress((void**)&woh, g_woh); cudaGetSymbolAddress((void**)&wol, g_wol);
    cudaGetSymbolAddress((void**)&w1h, g_w1h); cudaGetSymbolAddress((void**)&w1l, g_w1l);
    cudaGetSymbolAddress((void**)&w2h, g_w2h); cudaGetSymbolAddress((void**)&w2l, g_w2l);

    int attn_smem = 4 * 64 * SP * (int)sizeof(float);
    cudaFuncSetAttribute(attn_kernel,
                         cudaFuncAttributeMaxDynamicSharedMemorySize, attn_smem);
    cudaFuncSetAttribute(gemm_mma_kernel<0,0>,
                         cudaFuncAttributeMaxDynamicSharedMemorySize, GEMM_SMEM);
    cudaFuncSetAttribute(gemm_mma_kernel<1,1>,
                         cudaFuncAttributeMaxDynamicSharedMemorySize, GEMM_SMEM);

    // 1) RoPE(x) -> a1 hi/lo ; x -> a2 hi/lo ; weight splits
    rope_split_kernel<<<BS, 256>>>(x, a1h, a1l);
    split_kernel<<<(BS * E_) / 1024, 256>>>(x, a2h, a2l);
    split_kernel<<<(3 * E_ * E_) / 1024, 256>>>(ipw, wih, wil);
    split_kernel<<<(E_ * E_) / 1024, 256>>>(opw, woh, wol);
    split_kernel<<<(FF * E_) / 1024, 256>>>(w1, w1h, w1l);
    split_kernel<<<(FF * E_) / 1024, 256>>>(w2, w2h, w2l);

    // 2) fused Q|K GEMM (N=2048) + V GEMM
    gemm_mma_kernel<0,0><<<dim3(16, 64), 256, GEMM_SMEM>>>(
        a1h, a1l, wih, wil, ipb, qk, nullptr, nullptr, BS, 2 * E_, E_);
    gemm_mma_kernel<0,0><<<dim3(8, 64), 256, GEMM_SMEM>>>(
        a2h, a2l, wih + (size_t)2*E_*E_, wil + (size_t)2*E_*E_,
        ipb + 2 * E_, vb, nullptr, nullptr, BS, E_, E_);

    // 3) sliding-window attention -> ctx bf16 hi/lo (reuses a2h/a2l)
    attn_kernel<<<dim3(SS / 64, NH, BB), 256, attn_smem>>>(
        qk, qk + E_, vb, 2 * E_, a2h, a2l);

    // 4) out-proj, residual + LN1 -> x1 (+ fused split into a1h/a1l)
    gemm_mma_kernel<0,0><<<dim3(8, 64), 256, GEMM_SMEM>>>(
        a2h, a2l, woh, wol, opb, tmp, nullptr, nullptr, BS, E_, E_);
    add_ln_kernel<<<BS, 256>>>(x, tmp, ln1g, ln1b, x1, a1h, a1l);

    // 5) FFN: GELU GEMM emits bf16 hi/lo directly; FFN2 -> tmp; LN2 -> out
    gemm_mma_kernel<1,1><<<dim3(32, 64), 256, GEMM_SMEM>>>(
        a1h, a1l, w1h, w1l, b1, nullptr, hh, hl, BS, FF, E_);
    gemm_mma_kernel<0,0><<<dim3(8, 64), 256, GEMM_SMEM>>>(
        hh, hl, w2h, w2l, b2, tmp, nullptr, nullptr, BS, E_, FF);
    add_ln_kernel<<<BS, 256>>>(x1, tmp, ln2g, ln2b, out, nullptr, nullptr);
}

// round 6
// speedup vs baseline: 2.7230x; 1.2717x over previous
#include <cuda_runtime.h>
#include <cuda_fp16.h>
#include <math.h>
#include <stdint.h>

#define E_   1024
#define NH   16
#define HD   64
#define WIN  256
#define BB   8
#define SS   1024
#define BS   (BB*SS)
#define FF   4096
#define SP   68   // padded smem row stride (floats) for attention tiles

// ---------------- scratch ------------------------------------------------------
__device__ float g_v[BS*E_];
__device__ float g_tmp[BS*E_];
__device__ float g_x1[BS*E_];
__device__ float g_qk[(size_t)BS*2*E_];          // fused Q|K output

__device__ __half g_a1h[BS*E_], g_a1l[BS*E_];
__device__ __half g_a2h[BS*E_], g_a2l[BS*E_];
__device__ __half g_hh[(size_t)BS*FF], g_hl[(size_t)BS*FF];
__device__ __half g_wih[3*E_*E_];
__device__ __half g_woh[E_*E_];
__device__ __half g_w1h[FF*E_];
__device__ __half g_w2h[FF*E_];

// ---------------- helpers -------------------------------------------------------
__device__ __forceinline__ uint32_t smem_u32(const void* p) {
    uint32_t a;
    asm("{ .reg .u64 t; cvta.to.shared.u64 t, %1; cvt.u32.u64 %0, t; }" : "=r"(a) : "l"(p));
    return a;
}
__device__ __forceinline__ void cp16(uint32_t dst, const void* src) {
    asm volatile("cp.async.cg.shared.global [%0], [%1], 16;" :: "r"(dst), "l"(src));
}
__device__ __forceinline__ void cp_commit() { asm volatile("cp.async.commit_group;"); }
__device__ __forceinline__ void cp_wait2()  { asm volatile("cp.async.wait_group 2;" ::: "memory"); }
__device__ __forceinline__ void ldm_x4(uint32_t addr, uint32_t& r0, uint32_t& r1,
                                       uint32_t& r2, uint32_t& r3) {
    asm volatile("ldmatrix.sync.aligned.m8n8.x4.shared.b16 {%0,%1,%2,%3}, [%4];"
                 : "=r"(r0), "=r"(r1), "=r"(r2), "=r"(r3) : "r"(addr));
}
__device__ __forceinline__ void mma16816(float* c, const uint32_t* a, const uint32_t* b) {
    asm volatile(
        "mma.sync.aligned.m16n8k16.row.col.f32.f16.f16.f32 "
        "{%0,%1,%2,%3}, {%4,%5,%6,%7}, {%8,%9}, {%0,%1,%2,%3};"
        : "+f"(c[0]), "+f"(c[1]), "+f"(c[2]), "+f"(c[3])
        : "r"(a[0]), "r"(a[1]), "r"(a[2]), "r"(a[3]), "r"(b[0]), "r"(b[1]));
}
__device__ __forceinline__ void split1h(float v, unsigned short& h, unsigned short& l) {
    __half hb = __float2half_rn(v);
    __half lb = __float2half_rn(v - __half2float(hb));
    h = __half_as_ushort(hb);
    l = __half_as_ushort(lb);
}

// ---------------- split fp32 -> fp16 hi/lo --------------------------------------
__global__ __launch_bounds__(256) void split_kernel(const float* __restrict__ src,
                                                    __half* __restrict__ hi,
                                                    __half* __restrict__ lo)
{
    size_t i = ((size_t)blockIdx.x * 256 + threadIdx.x) * 4;
    float4 v = *(const float4*)&src[i];
    float vv[4] = {v.x, v.y, v.z, v.w};
    unsigned short hs[4], ls[4];
#pragma unroll
    for (int j = 0; j < 4; j++) split1h(vv[j], hs[j], ls[j]);
    uint2 ho, lo2;
    ho.x  = hs[0] | ((uint32_t)hs[1] << 16); ho.y  = hs[2] | ((uint32_t)hs[3] << 16);
    lo2.x = ls[0] | ((uint32_t)ls[1] << 16); lo2.y = ls[2] | ((uint32_t)ls[3] << 16);
    *(uint2*)&hi[i] = ho;
    *(uint2*)&lo[i] = lo2;
}

// ---------------- convert fp32 -> fp16 (weights, hi only) -----------------------
__global__ __launch_bounds__(256) void wconv_kernel(const float* __restrict__ src,
                                                    __half* __restrict__ hi)
{
    size_t i = ((size_t)blockIdx.x * 256 + threadIdx.x) * 4;
    float4 v = *(const float4*)&src[i];
    unsigned short hs[4];
    hs[0] = __half_as_ushort(__float2half_rn(v.x));
    hs[1] = __half_as_ushort(__float2half_rn(v.y));
    hs[2] = __half_as_ushort(__float2half_rn(v.z));
    hs[3] = __half_as_ushort(__float2half_rn(v.w));
    uint2 ho;
    ho.x = hs[0] | ((uint32_t)hs[1] << 16);
    ho.y = hs[2] | ((uint32_t)hs[3] << 16);
    *(uint2*)&hi[i] = ho;
}

// ---------------- RoPE on raw x -> fp16 hi/lo ------------------------------------
__global__ __launch_bounds__(256) void rope_split_kernel(const float* __restrict__ x,
                                                         __half* __restrict__ hi,
                                                         __half* __restrict__ lo)
{
    int tok = blockIdx.x;
    float pos = (float)(tok & (SS - 1));
    int base = tok * E_ + threadIdx.x * 4;
    int d = (threadIdx.x * 4) & (HD - 1);
    const float* xp = &x[base];
    float4 xv = *(const float4*)xp;
    float res[4];
    const float LOG2_10000 = 13.287712379549449f;
#pragma unroll
    for (int i = 0; i < 4; i++) {
        int dd = d + i;
        int j = (dd < 32) ? dd : dd - 32;
        float fr = exp2f(-(float)j * (2.0f / 64.0f) * LOG2_10000);
        float ang = pos * fr;
        float s, c;
        sincosf(ang, &s, &c);
        float v = ((const float*)&xv)[i];
        float other = (dd < 32) ? -xp[i + 32] : xp[i - 32];
        res[i] = v * c + other * s;
    }
    unsigned short hs[4], ls[4];
#pragma unroll
    for (int j = 0; j < 4; j++) split1h(res[j], hs[j], ls[j]);
    uint2 ho, lo2;
    ho.x  = hs[0] | ((uint32_t)hs[1] << 16); ho.y  = hs[2] | ((uint32_t)hs[3] << 16);
    lo2.x = ls[0] | ((uint32_t)ls[1] << 16); lo2.y = ls[2] | ((uint32_t)ls[3] << 16);
    *(uint2*)&hi[base] = ho;
    *(uint2*)&lo[base] = lo2;
}

// ---------------- HMMA fp16x2 GEMM: C[M,N] = A[M,K] @ W[N,K]^T + bias -----------
// CTA 128x128, 8 warps (4x2), m16n8k16, BK=32, 4-stage cp.async pipeline.
// 2 precision segments: Ah*Bh + Al*Bh (A-side fully corrected, fp32 accum).
// MODE 0: fp32 C out.  MODE 1: fp16 hi/lo out (fused split).  ACT 1: exact GELU.
#define STG 4
#define GEMM_SMEM (STG * 16384)

template<int ACT, int MODE>
__global__ __launch_bounds__(256, 2) void gemm_mma_kernel(
    const __half* __restrict__ Ah, const __half* __restrict__ Al,
    const __half* __restrict__ Bh,
    const float* __restrict__ bias, float* __restrict__ C,
    __half* __restrict__ Ch, __half* __restrict__ Cl,
    int M, int N, int K)
{
    extern __shared__ __align__(16) char smc[];   // A: STGx8KB @0, B: STGx8KB @STG*8192
    uint32_t sbase = smem_u32(smc);
    const uint32_t BOFF = STG * 8192;

    int t = threadIdx.x;
    int lane = t & 31, wid = t >> 5;
    int warp_m = wid & 3, warp_n = wid >> 2;
    int m0 = blockIdx.y * 128;
    int n0 = blockIdx.x * 128;

    // loader mapping (2 x 16B chunks per thread per matrix per stage)
    uint32_t aOff[2];
    size_t   aG[2], bG[2];
#pragma unroll
    for (int i = 0; i < 2; i++) {
        int idx = t + i * 256;
        int row = idx >> 2, ch = idx & 3;
        uint32_t swz = (uint32_t)(ch ^ ((row >> 1) & 3));
        aOff[i] = (uint32_t)(row * 64) + swz * 16;
        aG[i] = (size_t)(m0 + row) * K + ch * 8;
        bG[i] = (size_t)(n0 + row) * K + ch * 8;
    }

    // ldmatrix address components
    uint32_t aRow64[2]; int aRswz[2];
#pragma unroll
    for (int ti = 0; ti < 2; ti++) {
        int row = warp_m * 32 + ti * 16 + (lane & 15);
        aRow64[ti] = (uint32_t)(row * 64);
        aRswz[ti] = (row >> 1) & 3;
    }
    int aChunkBase = lane >> 4;
    uint32_t bRow64[4]; int bRswz[4];
#pragma unroll
    for (int j2 = 0; j2 < 4; j2++) {
        int row = warp_n * 64 + j2 * 16 + ((lane >> 4) << 3) + (lane & 7);
        bRow64[j2] = (uint32_t)(row * 64);
        bRswz[j2] = (row >> 1) & 3;
    }
    int bChunkBase = (lane >> 3) & 1;

    float acc[2][8][4];
#pragma unroll
    for (int mi = 0; mi < 2; mi++)
#pragma unroll
        for (int nj = 0; nj < 8; nj++)
#pragma unroll
            for (int r = 0; r < 4; r++) acc[mi][nj][r] = 0.f;

    const __half* Aseg[2] = {Ah, Al};
    int KC = K >> 5;
    int NC = 2 * KC;

    // prologue: chunks 0..2 -> stages 0..2
#pragma unroll
    for (int p = 0; p < 3; p++) {
        int seg = (p >= KC) ? 1 : 0;
        size_t ko = (size_t)(p - seg * KC) * 32;
        const __half* Ap = Aseg[seg];
        uint32_t sa = sbase + (uint32_t)p * 8192;
        uint32_t sb = sbase + BOFF + (uint32_t)p * 8192;
#pragma unroll
        for (int i = 0; i < 2; i++) cp16(sa + aOff[i], Ap + aG[i] + ko);
#pragma unroll
        for (int i = 0; i < 2; i++) cp16(sb + aOff[i], Bh + bG[i] + ko);
        cp_commit();
    }

    for (int c = 0; c < NC; c++) {
        cp_wait2();
        __syncthreads();

        if (c + 3 < NC) {
            int cn = c + 3;
            int seg = (cn >= KC) ? 1 : 0;
            size_t ko = (size_t)(cn - seg * KC) * 32;
            const __half* Ap = Aseg[seg];
            uint32_t st = (uint32_t)(cn & (STG - 1));
            uint32_t sa = sbase + st * 8192;
            uint32_t sb = sbase + BOFF + st * 8192;
#pragma unroll
            for (int i = 0; i < 2; i++) cp16(sa + aOff[i], Ap + aG[i] + ko);
#pragma unroll
            for (int i = 0; i < 2; i++) cp16(sb + aOff[i], Bh + bG[i] + ko);
        }
        cp_commit();

        uint32_t sa = sbase + (uint32_t)(c & (STG - 1)) * 8192;
        uint32_t sb = sbase + BOFF + (uint32_t)(c & (STG - 1)) * 8192;
#pragma unroll
        for (int kstep = 0; kstep < 2; kstep++) {
            uint32_t a[2][4], b[4][4];
#pragma unroll
            for (int ti = 0; ti < 2; ti++) {
                int ch = kstep * 2 + aChunkBase;
                uint32_t addr = sa + aRow64[ti] + (uint32_t)((ch ^ aRswz[ti]) * 16);
                ldm_x4(addr, a[ti][0], a[ti][1], a[ti][2], a[ti][3]);
            }
#pragma unroll
            for (int j2 = 0; j2 < 4; j2++) {
                int ch = kstep * 2 + bChunkBase;
                uint32_t addr = sb + bRow64[j2] + (uint32_t)((ch ^ bRswz[j2]) * 16);
                ldm_x4(addr, b[j2][0], b[j2][1], b[j2][2], b[j2][3]);
            }
#pragma unroll
            for (int mi = 0; mi < 2; mi++)
#pragma unroll
                for (int nj = 0; nj < 8; nj++)
                    mma16816(acc[mi][nj], a[mi], &b[nj >> 1][(nj & 1) * 2]);
        }
    }

    // ---- epilogue
    int tq = lane >> 2, tr = lane & 3;
#pragma unroll
    for (int mi = 0; mi < 2; mi++) {
#pragma unroll
        for (int nj = 0; nj < 8; nj++) {
            int row0 = m0 + warp_m * 32 + mi * 16 + tq;
            int col = n0 + warp_n * 64 + nj * 8 + tr * 2;
            float b0 = __ldg(&bias[col]), b1 = __ldg(&bias[col + 1]);
            float v0 = acc[mi][nj][0] + b0, v1 = acc[mi][nj][1] + b1;
            float v2 = acc[mi][nj][2] + b0, v3 = acc[mi][nj][3] + b1;
            if (ACT) {
                v0 = 0.5f * v0 * (1.0f + erff(v0 * 0.70710678118654752f));
                v1 = 0.5f * v1 * (1.0f + erff(v1 * 0.70710678118654752f));
                v2 = 0.5f * v2 * (1.0f + erff(v2 * 0.70710678118654752f));
                v3 = 0.5f * v3 * (1.0f + erff(v3 * 0.70710678118654752f));
            }
            if (MODE == 0) {
                *(float2*)&C[(size_t)row0 * N + col] = make_float2(v0, v1);
                *(float2*)&C[(size_t)(row0 + 8) * N + col] = make_float2(v2, v3);
            } else {
                unsigned short h0, l0, h1, l1, h2, l2, h3, l3;
                split1h(v0, h0, l0); split1h(v1, h1, l1);
                split1h(v2, h2, l2); split1h(v3, h3, l3);
                *(uint32_t*)&Ch[(size_t)row0 * N + col] = h0 | ((uint32_t)h1 << 16);
                *(uint32_t*)&Cl[(size_t)row0 * N + col] = l0 | ((uint32_t)l1 << 16);
                *(uint32_t*)&Ch[(size_t)(row0 + 8) * N + col] = h2 | ((uint32_t)h3 << 16);
                *(uint32_t*)&Cl[(size_t)(row0 + 8) * N + col] = l2 | ((uint32_t)l3 << 16);
            }
        }
    }
}

// ---------------- sliding-window attention -> fp16 hi/lo ctx --------------------
__global__ __launch_bounds__(256) void attn_kernel(
    const float* __restrict__ q, const float* __restrict__ k,
    const float* __restrict__ v, int qks,
    __half* __restrict__ ch, __half* __restrict__ cl)
{
    extern __shared__ float sm[];
    float* q_s = sm;
    float* k_s = q_s + 64 * SP;
    float* v_s = k_s + 64 * SP;
    float* p_s = v_s + 64 * SP;

    int b = blockIdx.z, h = blockIdx.y;
    int q0 = blockIdx.x * 64;
    int t = threadIdx.x;
    int tq = t >> 4, tk = t & 15;

#pragma unroll
    for (int i = 0; i < 4; i++) {
        int l = t + i * 256;
        int r = l >> 4;
        int c = (l & 15) * 4;
        *(float4*)&q_s[r * SP + c] =
            *(const float4*)&q[((size_t)(b * SS + q0 + r)) * qks + h * HD + c];
    }

    float m[4], lsum[4], acc[4][4];
#pragma unroll
    for (int i = 0; i < 4; i++) {
        m[i] = -1e30f; lsum[i] = 0.f;
#pragma unroll
        for (int j = 0; j < 4; j++) acc[i][j] = 0.f;
    }

    int kstart = q0 - WIN; if (kstart < 0) kstart = 0;
    int kend = q0 + 64 + WIN; if (kend > SS) kend = SS;
    const float scale = 0.125f;

    for (int kb = kstart; kb < kend; kb += 64) {
        __syncthreads();
#pragma unroll
        for (int i = 0; i < 4; i++) {
            int l = t + i * 256;
            int r = l >> 4;
            int c = (l & 15) * 4;
            *(float4*)&k_s[r * SP + c] =
                *(const float4*)&k[((size_t)(b * SS + kb + r)) * qks + h * HD + c];
            *(float4*)&v_s[r * SP + c] =
                *(const float4*)&v[((size_t)(b * SS + kb + r)) * E_ + h * HD + c];
        }
        __syncthreads();

        float s[4][4];
#pragma unroll
        for (int i = 0; i < 4; i++)
#pragma unroll
            for (int j = 0; j < 4; j++) s[i][j] = 0.f;
#pragma unroll
        for (int d4 = 0; d4 < 16; d4++) {
            float4 qv[4], kv[4];
#pragma unroll
            for (int i = 0; i < 4; i++)
                qv[i] = *(const float4*)&q_s[(tq * 4 + i) * SP + d4 * 4];
#pragma unroll
            for (int j = 0; j < 4; j++)
                kv[j] = *(const float4*)&k_s[(tk * 4 + j) * SP + d4 * 4];
#pragma unroll
            for (int i = 0; i < 4; i++)
#pragma unroll
                for (int j = 0; j < 4; j++)
                    s[i][j] += qv[i].x * kv[j].x + qv[i].y * kv[j].y +
                               qv[i].z * kv[j].z + qv[i].w * kv[j].w;
        }

#pragma unroll
        for (int i = 0; i < 4; i++) {
            int qi = q0 + tq * 4 + i;
            float rmax = -1e30f;
#pragma unroll
            for (int j = 0; j < 4; j++) {
                int diff = qi - (kb + tk * 4 + j);
                bool ok = (diff <= WIN) && (diff >= -WIN);
                s[i][j] = ok ? s[i][j] * scale : -1e30f;
                rmax = fmaxf(rmax, s[i][j]);
            }
            rmax = fmaxf(rmax, __shfl_xor_sync(0xffffffffu, rmax, 1));
            rmax = fmaxf(rmax, __shfl_xor_sync(0xffffffffu, rmax, 2));
            rmax = fmaxf(rmax, __shfl_xor_sync(0xffffffffu, rmax, 4));
            rmax = fmaxf(rmax, __shfl_xor_sync(0xffffffffu, rmax, 8));
            float mnew = fmaxf(m[i], rmax);
            float corr = expf(m[i] - mnew);
            float rsum = 0.f;
#pragma unroll
            for (int j = 0; j < 4; j++) {
                float p = (s[i][j] > -1e29f) ? expf(s[i][j] - mnew) : 0.f;
                p_s[(tq * 4 + i) * SP + tk * 4 + j] = p;
                rsum += p;
            }
            rsum += __shfl_xor_sync(0xffffffffu, rsum, 1);
            rsum += __shfl_xor_sync(0xffffffffu, rsum, 2);
            rsum += __shfl_xor_sync(0xffffffffu, rsum, 4);
            rsum += __shfl_xor_sync(0xffffffffu, rsum, 8);
            m[i] = mnew;
            lsum[i] = lsum[i] * corr + rsum;
#pragma unroll
            for (int j = 0; j < 4; j++) acc[i][j] *= corr;
        }
        __syncthreads();

#pragma unroll 4
        for (int kk = 0; kk < 64; kk++) {
            float4 vv = *(const float4*)&v_s[kk * SP + tk * 4];
#pragma unroll
            for (int i = 0; i < 4; i++) {
                float p = p_s[(tq * 4 + i) * SP + kk];
                acc[i][0] += p * vv.x; acc[i][1] += p * vv.y;
                acc[i][2] += p * vv.z; acc[i][3] += p * vv.w;
            }
        }
    }

#pragma unroll
    for (int i = 0; i < 4; i++) {
        float inv = 1.f / lsum[i];
        size_t o = ((size_t)(b * SS + q0 + tq * 4 + i)) * E_ + h * HD + tk * 4;
        unsigned short hs[4], ls[4];
#pragma unroll
        for (int j = 0; j < 4; j++) split1h(acc[i][j] * inv, hs[j], ls[j]);
        uint2 ho, lo2;
        ho.x  = hs[0] | ((uint32_t)hs[1] << 16); ho.y  = hs[2] | ((uint32_t)hs[3] << 16);
        lo2.x = ls[0] | ((uint32_t)ls[1] << 16); lo2.y = ls[2] | ((uint32_t)ls[3] << 16);
        *(uint2*)&ch[o] = ho;
        *(uint2*)&cl[o] = lo2;
    }
}

// ---------------- residual add + LayerNorm (optional fused fp16 split) ----------
__global__ __launch_bounds__(256) void add_ln_kernel(
    const float* __restrict__ a, const float* __restrict__ r,
    const float* __restrict__ g, const float* __restrict__ be,
    float* __restrict__ out,
    __half* __restrict__ oh, __half* __restrict__ ol)
{
    int row = blockIdx.x;
    int t = threadIdx.x;
    size_t base = (size_t)row * E_;
    float4 av = *(const float4*)&a[base + t * 4];
    float4 rv = *(const float4*)&r[base + t * 4];
    float v0 = av.x + rv.x, v1 = av.y + rv.y, v2 = av.z + rv.z, v3 = av.w + rv.w;
    float sum = v0 + v1 + v2 + v3;
    float sq = v0 * v0 + v1 * v1 + v2 * v2 + v3 * v3;
#pragma unroll
    for (int off = 16; off; off >>= 1) {
        sum += __shfl_xor_sync(0xffffffffu, sum, off);
        sq  += __shfl_xor_sync(0xffffffffu, sq, off);
    }
    __shared__ float ss[8], sq2[8], stat[2];
    int w = t >> 5;
    if ((t & 31) == 0) { ss[w] = sum; sq2[w] = sq; }
    __syncthreads();
    if (t == 0) {
        float S1 = 0.f, S2 = 0.f;
        for (int i = 0; i < 8; i++) { S1 += ss[i]; S2 += sq2[i]; }
        float mean = S1 * (1.0f / E_);
        float var = S2 * (1.0f / E_) - mean * mean;
        stat[0] = mean;
        stat[1] = rsqrtf(var + 1e-5f);
    }
    __syncthreads();
    float mean = stat[0], rstd = stat[1];
    float4 gv = *(const float4*)&g[t * 4];
    float4 bv = *(const float4*)&be[t * 4];
    float o[4];
    o[0] = (v0 - mean) * rstd * gv.x + bv.x;
    o[1] = (v1 - mean) * rstd * gv.y + bv.y;
    o[2] = (v2 - mean) * rstd * gv.z + bv.z;
    o[3] = (v3 - mean) * rstd * gv.w + bv.w;
    *(float4*)&out[base + t * 4] = make_float4(o[0], o[1], o[2], o[3]);
    if (oh) {
        unsigned short hs[4], ls[4];
#pragma unroll
        for (int j = 0; j < 4; j++) split1h(o[j], hs[j], ls[j]);
        uint2 ho, lo2;
        ho.x  = hs[0] | ((uint32_t)hs[1] << 16); ho.y  = hs[2] | ((uint32_t)hs[3] << 16);
        lo2.x = ls[0] | ((uint32_t)ls[1] << 16); lo2.y = ls[2] | ((uint32_t)ls[3] << 16);
        *(uint2*)&oh[base + t * 4] = ho;
        *(uint2*)&ol[base + t * 4] = lo2;
    }
}

// ---------------- launch ---------------------------------------------------------
extern "C" void kernel_launch(void* const* d_in, const int* in_sizes, int n_in,
                              void* d_out, int out_size)
{
    (void)in_sizes; (void)n_in; (void)out_size;
    const float* x    = (const float*)d_in[0];
    const float* ipw  = (const float*)d_in[1];
    const float* ipb  = (const float*)d_in[2];
    const float* opw  = (const float*)d_in[3];
    const float* opb  = (const float*)d_in[4];
    const float* ln1g = (const float*)d_in[5];
    const float* ln1b = (const float*)d_in[6];
    const float* w1   = (const float*)d_in[7];
    const float* b1   = (const float*)d_in[8];
    const float* w2   = (const float*)d_in[9];
    const float* b2   = (const float*)d_in[10];
    const float* ln2g = (const float*)d_in[11];
    const float* ln2b = (const float*)d_in[12];
    float* out = (float*)d_out;

    float *vb, *tmp, *x1, *qk;
    cudaGetSymbolAddress((void**)&vb,  g_v);
    cudaGetSymbolAddress((void**)&tmp, g_tmp);
    cudaGetSymbolAddress((void**)&x1,  g_x1);
    cudaGetSymbolAddress((void**)&qk,  g_qk);

    __half *a1h, *a1l, *a2h, *a2l, *hh, *hl, *wih, *woh, *w1h, *w2h;
    cudaGetSymbolAddress((void**)&a1h, g_a1h); cudaGetSymbolAddress((void**)&a1l, g_a1l);
    cudaGetSymbolAddress((void**)&a2h, g_a2h); cudaGetSymbolAddress((void**)&a2l, g_a2l);
    cudaGetSymbolAddress((void**)&hh,  g_hh);  cudaGetSymbolAddress((void**)&hl,  g_hl);
    cudaGetSymbolAddress((void**)&wih, g_wih); cudaGetSymbolAddress((void**)&woh, g_woh);
    cudaGetSymbolAddress((void**)&w1h, g_w1h); cudaGetSymbolAddress((void**)&w2h, g_w2h);

    int attn_smem = 4 * 64 * SP * (int)sizeof(float);
    cudaFuncSetAttribute(attn_kernel,
                         cudaFuncAttributeMaxDynamicSharedMemorySize, attn_smem);
    cudaFuncSetAttribute(gemm_mma_kernel<0,0>,
                         cudaFuncAttributeMaxDynamicSharedMemorySize, GEMM_SMEM);
    cudaFuncSetAttribute(gemm_mma_kernel<1,1>,
                         cudaFuncAttributeMaxDynamicSharedMemorySize, GEMM_SMEM);

    // launch order keeps the fused Q|K GEMM at index 5 (ncu -s 5 -c 1 profiles it)
    rope_split_kernel<<<BS, 256>>>(x, a1h, a1l);                       // 0
    split_kernel<<<(BS * E_) / 1024, 256>>>(x, a2h, a2l);              // 1
    wconv_kernel<<<(3 * E_ * E_) / 1024, 256>>>(ipw, wih);             // 2
    wconv_kernel<<<(E_ * E_) / 1024, 256>>>(opw, woh);                 // 3
    wconv_kernel<<<(FF * E_) / 1024, 256>>>(w1, w1h);                  // 4

    // 5: fused Q|K GEMM (N=2048)  <-- profiled launch
    gemm_mma_kernel<0,0><<<dim3(16, 64), 256, GEMM_SMEM>>>(
        a1h, a1l, wih, ipb, qk, nullptr, nullptr, BS, 2 * E_, E_);

    wconv_kernel<<<(FF * E_) / 1024, 256>>>(w2, w2h);                  // 6

    // V GEMM
    gemm_mma_kernel<0,0><<<dim3(8, 64), 256, GEMM_SMEM>>>(
        a2h, a2l, wih + (size_t)2*E_*E_, ipb + 2 * E_, vb, nullptr, nullptr, BS, E_, E_);

    // attention -> ctx fp16 hi/lo (reuses a2h/a2l)
    attn_kernel<<<dim3(SS / 64, NH, BB), 256, attn_smem>>>(
        qk, qk + E_, vb, 2 * E_, a2h, a2l);

    // out-proj, residual + LN1 -> x1 (+ fused split into a1h/a1l)
    gemm_mma_kernel<0,0><<<dim3(8, 64), 256, GEMM_SMEM>>>(
        a2h, a2l, woh, opb, tmp, nullptr, nullptr, BS, E_, E_);
    add_ln_kernel<<<BS, 256>>>(x, tmp, ln1g, ln1b, x1, a1h, a1l);

    // FFN
    gemm_mma_kernel<1,1><<<dim3(32, 64), 256, GEMM_SMEM>>>(
        a1h, a1l, w1h, b1, nullptr, hh, hl, BS, FF, E_);
    gemm_mma_kernel<0,0><<<dim3(8, 64), 256, GEMM_SMEM>>>(
        hh, hl, w2h, b2, tmp, nullptr, nullptr, BS, E_, FF);
    add_ln_kernel<<<BS, 256>>>(x1, tmp, ln2g, ln2b, out, nullptr, nullptr);
}

// round 7
// speedup vs baseline: 3.7644x; 1.3824x over previous
#include <cuda_runtime.h>
#include <cuda_fp16.h>
#include <math.h>
#include <stdint.h>

#define E_   1024
#define NH   16
#define HD   64
#define WIN  256
#define BB   8
#define SS   1024
#define BS   (BB*SS)
#define FF   4096
#define SP   68   // padded smem row stride (floats) for attention tiles

// ---------------- scratch ------------------------------------------------------
__device__ float g_v[BS*E_];
__device__ float g_tmp[BS*E_];
__device__ float g_x1[BS*E_];
__device__ float g_qk[(size_t)BS*2*E_];          // fused Q|K output

__device__ __half g_a1h[BS*E_];                  // roped input (fp16)
__device__ __half g_a2h[BS*E_];                  // x / ctx (fp16, reused)
__device__ __half g_x1h[BS*E_];                  // x1 (fp16)
__device__ __half g_hh[(size_t)BS*FF];           // GELU(ffn1) (fp16)
__device__ __half g_wih[3*E_*E_];
__device__ __half g_woh[E_*E_];
__device__ __half g_w1h[FF*E_];
__device__ __half g_w2h[FF*E_];

// ---------------- helpers -------------------------------------------------------
__device__ __forceinline__ uint32_t smem_u32(const void* p) {
    uint32_t a;
    asm("{ .reg .u64 t; cvta.to.shared.u64 t, %1; cvt.u32.u64 %0, t; }" : "=r"(a) : "l"(p));
    return a;
}
__device__ __forceinline__ void cp16(uint32_t dst, const void* src) {
    asm volatile("cp.async.cg.shared.global [%0], [%1], 16;" :: "r"(dst), "l"(src));
}
__device__ __forceinline__ void cp_commit() { asm volatile("cp.async.commit_group;"); }
__device__ __forceinline__ void cp_wait2()  { asm volatile("cp.async.wait_group 2;" ::: "memory"); }
__device__ __forceinline__ void ldm_x4(uint32_t addr, uint32_t& r0, uint32_t& r1,
                                       uint32_t& r2, uint32_t& r3) {
    asm volatile("ldmatrix.sync.aligned.m8n8.x4.shared.b16 {%0,%1,%2,%3}, [%4];"
                 : "=r"(r0), "=r"(r1), "=r"(r2), "=r"(r3) : "r"(addr));
}
__device__ __forceinline__ void mma16816(float* c, const uint32_t* a, const uint32_t* b) {
    asm volatile(
        "mma.sync.aligned.m16n8k16.row.col.f32.f16.f16.f32 "
        "{%0,%1,%2,%3}, {%4,%5,%6,%7}, {%8,%9}, {%0,%1,%2,%3};"
        : "+f"(c[0]), "+f"(c[1]), "+f"(c[2]), "+f"(c[3])
        : "r"(a[0]), "r"(a[1]), "r"(a[2]), "r"(a[3]), "r"(b[0]), "r"(b[1]));
}
__device__ __forceinline__ uint32_t pack_h2(float a, float b) {
    __half2 h = __floats2half2_rn(a, b);
    return *(uint32_t*)&h;
}

// ---------------- convert fp32 -> fp16 -------------------------------------------
__global__ __launch_bounds__(256) void conv_kernel(const float* __restrict__ src,
                                                   __half* __restrict__ hi)
{
    size_t i = ((size_t)blockIdx.x * 256 + threadIdx.x) * 4;
    float4 v = *(const float4*)&src[i];
    uint2 ho;
    ho.x = pack_h2(v.x, v.y);
    ho.y = pack_h2(v.z, v.w);
    *(uint2*)&hi[i] = ho;
}

// ---------------- RoPE on raw x -> fp16 ------------------------------------------
__global__ __launch_bounds__(256) void rope_conv_kernel(const float* __restrict__ x,
                                                        __half* __restrict__ hi)
{
    int tok = blockIdx.x;
    float pos = (float)(tok & (SS - 1));
    int base = tok * E_ + threadIdx.x * 4;
    int d = (threadIdx.x * 4) & (HD - 1);
    const float* xp = &x[base];
    float4 xv = *(const float4*)xp;
    float res[4];
    const float LOG2_10000 = 13.287712379549449f;
#pragma unroll
    for (int i = 0; i < 4; i++) {
        int dd = d + i;
        int j = (dd < 32) ? dd : dd - 32;
        float fr = exp2f(-(float)j * (2.0f / 64.0f) * LOG2_10000);
        float ang = pos * fr;
        float s, c;
        sincosf(ang, &s, &c);
        float v = ((const float*)&xv)[i];
        float other = (dd < 32) ? -xp[i + 32] : xp[i - 32];
        res[i] = v * c + other * s;
    }
    uint2 ho;
    ho.x = pack_h2(res[0], res[1]);
    ho.y = pack_h2(res[2], res[3]);
    *(uint2*)&hi[base] = ho;
}

// ---------------- HMMA fp16 GEMM: C[M,N] = A[M,K] @ W[N,K]^T + bias --------------
// CTA 128x128, 8 warps (4x2), m16n8k16, BK=32, 4-stage cp.async pipeline.
// MODE 0: fp32 C out.  MODE 1: fp16 C out.  ACT 1: exact GELU.
#define STG 4
#define GEMM_SMEM (STG * 16384)

template<int ACT, int MODE>
__global__ __launch_bounds__(256, 2) void gemm_mma_kernel(
    const __half* __restrict__ Ah, const __half* __restrict__ Bh,
    const float* __restrict__ bias, float* __restrict__ C,
    __half* __restrict__ Ch,
    int M, int N, int K)
{
    extern __shared__ __align__(16) char smc[];   // A: STGx8KB @0, B: STGx8KB @STG*8192
    uint32_t sbase = smem_u32(smc);
    const uint32_t BOFF = STG * 8192;

    int t = threadIdx.x;
    int lane = t & 31, wid = t >> 5;
    int warp_m = wid & 3, warp_n = wid >> 2;
    int m0 = blockIdx.y * 128;
    int n0 = blockIdx.x * 128;

    // loader mapping (2 x 16B chunks per thread per matrix per stage)
    uint32_t aOff[2];
    size_t   aG[2], bG[2];
#pragma unroll
    for (int i = 0; i < 2; i++) {
        int idx = t + i * 256;
        int row = idx >> 2, ch = idx & 3;
        uint32_t swz = (uint32_t)(ch ^ ((row >> 1) & 3));
        aOff[i] = (uint32_t)(row * 64) + swz * 16;
        aG[i] = (size_t)(m0 + row) * K + ch * 8;
        bG[i] = (size_t)(n0 + row) * K + ch * 8;
    }

    // ldmatrix address components
    uint32_t aRow64[2]; int aRswz[2];
#pragma unroll
    for (int ti = 0; ti < 2; ti++) {
        int row = warp_m * 32 + ti * 16 + (lane & 15);
        aRow64[ti] = (uint32_t)(row * 64);
        aRswz[ti] = (row >> 1) & 3;
    }
    int aChunkBase = lane >> 4;
    uint32_t bRow64[4]; int bRswz[4];
#pragma unroll
    for (int j2 = 0; j2 < 4; j2++) {
        int row = warp_n * 64 + j2 * 16 + ((lane >> 4) << 3) + (lane & 7);
        bRow64[j2] = (uint32_t)(row * 64);
        bRswz[j2] = (row >> 1) & 3;
    }
    int bChunkBase = (lane >> 3) & 1;

    float acc[2][8][4];
#pragma unroll
    for (int mi = 0; mi < 2; mi++)
#pragma unroll
        for (int nj = 0; nj < 8; nj++)
#pragma unroll
            for (int r = 0; r < 4; r++) acc[mi][nj][r] = 0.f;

    int NC = K >> 5;

    // prologue: chunks 0..2 -> stages 0..2
#pragma unroll
    for (int p = 0; p < 3; p++) {
        size_t ko = (size_t)p * 32;
        uint32_t sa = sbase + (uint32_t)p * 8192;
        uint32_t sb = sbase + BOFF + (uint32_t)p * 8192;
#pragma unroll
        for (int i = 0; i < 2; i++) cp16(sa + aOff[i], Ah + aG[i] + ko);
#pragma unroll
        for (int i = 0; i < 2; i++) cp16(sb + aOff[i], Bh + bG[i] + ko);
        cp_commit();
    }

    for (int c = 0; c < NC; c++) {
        cp_wait2();
        __syncthreads();

        if (c + 3 < NC) {
            size_t ko = (size_t)(c + 3) * 32;
            uint32_t st = (uint32_t)((c + 3) & (STG - 1));
            uint32_t sa = sbase + st * 8192;
            uint32_t sb = sbase + BOFF + st * 8192;
#pragma unroll
            for (int i = 0; i < 2; i++) cp16(sa + aOff[i], Ah + aG[i] + ko);
#pragma unroll
            for (int i = 0; i < 2; i++) cp16(sb + aOff[i], Bh + bG[i] + ko);
        }
        cp_commit();

        uint32_t sa = sbase + (uint32_t)(c & (STG - 1)) * 8192;
        uint32_t sb = sbase + BOFF + (uint32_t)(c & (STG - 1)) * 8192;
#pragma unroll
        for (int kstep = 0; kstep < 2; kstep++) {
            uint32_t a[2][4], b[4][4];
#pragma unroll
            for (int ti = 0; ti < 2; ti++) {
                int ch = kstep * 2 + aChunkBase;
                uint32_t addr = sa + aRow64[ti] + (uint32_t)((ch ^ aRswz[ti]) * 16);
                ldm_x4(addr, a[ti][0], a[ti][1], a[ti][2], a[ti][3]);
            }
#pragma unroll
            for (int j2 = 0; j2 < 4; j2++) {
                int ch = kstep * 2 + bChunkBase;
                uint32_t addr = sb + bRow64[j2] + (uint32_t)((ch ^ bRswz[j2]) * 16);
                ldm_x4(addr, b[j2][0], b[j2][1], b[j2][2], b[j2][3]);
            }
#pragma unroll
            for (int mi = 0; mi < 2; mi++)
#pragma unroll
                for (int nj = 0; nj < 8; nj++)
                    mma16816(acc[mi][nj], a[mi], &b[nj >> 1][(nj & 1) * 2]);
        }
    }

    // ---- epilogue
    int tq = lane >> 2, tr = lane & 3;
#pragma unroll
    for (int mi = 0; mi < 2; mi++) {
#pragma unroll
        for (int nj = 0; nj < 8; nj++) {
            int row0 = m0 + warp_m * 32 + mi * 16 + tq;
            int col = n0 + warp_n * 64 + nj * 8 + tr * 2;
            float b0 = __ldg(&bias[col]), b1 = __ldg(&bias[col + 1]);
            float v0 = acc[mi][nj][0] + b0, v1 = acc[mi][nj][1] + b1;
            float v2 = acc[mi][nj][2] + b0, v3 = acc[mi][nj][3] + b1;
            if (ACT) {
                v0 = 0.5f * v0 * (1.0f + erff(v0 * 0.70710678118654752f));
                v1 = 0.5f * v1 * (1.0f + erff(v1 * 0.70710678118654752f));
                v2 = 0.5f * v2 * (1.0f + erff(v2 * 0.70710678118654752f));
                v3 = 0.5f * v3 * (1.0f + erff(v3 * 0.70710678118654752f));
            }
            if (MODE == 0) {
                *(float2*)&C[(size_t)row0 * N + col] = make_float2(v0, v1);
                *(float2*)&C[(size_t)(row0 + 8) * N + col] = make_float2(v2, v3);
            } else {
                *(uint32_t*)&Ch[(size_t)row0 * N + col] = pack_h2(v0, v1);
                *(uint32_t*)&Ch[(size_t)(row0 + 8) * N + col] = pack_h2(v2, v3);
            }
        }
    }
}

// ---------------- sliding-window attention -> fp16 ctx ---------------------------
__global__ __launch_bounds__(256) void attn_kernel(
    const float* __restrict__ q, const float* __restrict__ k,
    const float* __restrict__ v, int qks,
    __half* __restrict__ ch)
{
    extern __shared__ float sm[];
    float* q_s = sm;
    float* k_s = q_s + 64 * SP;
    float* v_s = k_s + 64 * SP;
    float* p_s = v_s + 64 * SP;

    int b = blockIdx.z, h = blockIdx.y;
    int q0 = blockIdx.x * 64;
    int t = threadIdx.x;
    int tq = t >> 4, tk = t & 15;

#pragma unroll
    for (int i = 0; i < 4; i++) {
        int l = t + i * 256;
        int r = l >> 4;
        int c = (l & 15) * 4;
        *(float4*)&q_s[r * SP + c] =
            *(const float4*)&q[((size_t)(b * SS + q0 + r)) * qks + h * HD + c];
    }

    float m[4], lsum[4], acc[4][4];
#pragma unroll
    for (int i = 0; i < 4; i++) {
        m[i] = -1e30f; lsum[i] = 0.f;
#pragma unroll
        for (int j = 0; j < 4; j++) acc[i][j] = 0.f;
    }

    int kstart = q0 - WIN; if (kstart < 0) kstart = 0;
    int kend = q0 + 64 + WIN; if (kend > SS) kend = SS;
    const float scale = 0.125f;

    for (int kb = kstart; kb < kend; kb += 64) {
        __syncthreads();
#pragma unroll
        for (int i = 0; i < 4; i++) {
            int l = t + i * 256;
            int r = l >> 4;
            int c = (l & 15) * 4;
            *(float4*)&k_s[r * SP + c] =
                *(const float4*)&k[((size_t)(b * SS + kb + r)) * qks + h * HD + c];
            *(float4*)&v_s[r * SP + c] =
                *(const float4*)&v[((size_t)(b * SS + kb + r)) * E_ + h * HD + c];
        }
        __syncthreads();

        float s[4][4];
#pragma unroll
        for (int i = 0; i < 4; i++)
#pragma unroll
            for (int j = 0; j < 4; j++) s[i][j] = 0.f;
#pragma unroll
        for (int d4 = 0; d4 < 16; d4++) {
            float4 qv[4], kv[4];
#pragma unroll
            for (int i = 0; i < 4; i++)
                qv[i] = *(const float4*)&q_s[(tq * 4 + i) * SP + d4 * 4];
#pragma unroll
            for (int j = 0; j < 4; j++)
                kv[j] = *(const float4*)&k_s[(tk * 4 + j) * SP + d4 * 4];
#pragma unroll
            for (int i = 0; i < 4; i++)
#pragma unroll
                for (int j = 0; j < 4; j++)
                    s[i][j] += qv[i].x * kv[j].x + qv[i].y * kv[j].y +
                               qv[i].z * kv[j].z + qv[i].w * kv[j].w;
        }

#pragma unroll
        for (int i = 0; i < 4; i++) {
            int qi = q0 + tq * 4 + i;
            float rmax = -1e30f;
#pragma unroll
            for (int j = 0; j < 4; j++) {
                int diff = qi - (kb + tk * 4 + j);
                bool ok = (diff <= WIN) && (diff >= -WIN);
                s[i][j] = ok ? s[i][j] * scale : -1e30f;
                rmax = fmaxf(rmax, s[i][j]);
            }
            rmax = fmaxf(rmax, __shfl_xor_sync(0xffffffffu, rmax, 1));
            rmax = fmaxf(rmax, __shfl_xor_sync(0xffffffffu, rmax, 2));
            rmax = fmaxf(rmax, __shfl_xor_sync(0xffffffffu, rmax, 4));
            rmax = fmaxf(rmax, __shfl_xor_sync(0xffffffffu, rmax, 8));
            float mnew = fmaxf(m[i], rmax);
            float corr = expf(m[i] - mnew);
            float rsum = 0.f;
#pragma unroll
            for (int j = 0; j < 4; j++) {
                float p = (s[i][j] > -1e29f) ? expf(s[i][j] - mnew) : 0.f;
                p_s[(tq * 4 + i) * SP + tk * 4 + j] = p;
                rsum += p;
            }
            rsum += __shfl_xor_sync(0xffffffffu, rsum, 1);
            rsum += __shfl_xor_sync(0xffffffffu, rsum, 2);
            rsum += __shfl_xor_sync(0xffffffffu, rsum, 4);
            rsum += __shfl_xor_sync(0xffffffffu, rsum, 8);
            m[i] = mnew;
            lsum[i] = lsum[i] * corr + rsum;
#pragma unroll
            for (int j = 0; j < 4; j++) acc[i][j] *= corr;
        }
        __syncthreads();

#pragma unroll 4
        for (int kk = 0; kk < 64; kk++) {
            float4 vv = *(const float4*)&v_s[kk * SP + tk * 4];
#pragma unroll
            for (int i = 0; i < 4; i++) {
                float p = p_s[(tq * 4 + i) * SP + kk];
                acc[i][0] += p * vv.x; acc[i][1] += p * vv.y;
                acc[i][2] += p * vv.z; acc[i][3] += p * vv.w;
            }
        }
    }

#pragma unroll
    for (int i = 0; i < 4; i++) {
        float inv = 1.f / lsum[i];
        size_t o = ((size_t)(b * SS + q0 + tq * 4 + i)) * E_ + h * HD + tk * 4;
        uint2 ho;
        ho.x = pack_h2(acc[i][0] * inv, acc[i][1] * inv);
        ho.y = pack_h2(acc[i][2] * inv, acc[i][3] * inv);
        *(uint2*)&ch[o] = ho;
    }
}

// ---------------- residual add + LayerNorm (optional fused fp16 out) -------------
__global__ __launch_bounds__(256) void add_ln_kernel(
    const float* __restrict__ a, const float* __restrict__ r,
    const float* __restrict__ g, const float* __restrict__ be,
    float* __restrict__ out, __half* __restrict__ oh)
{
    int row = blockIdx.x;
    int t = threadIdx.x;
    size_t base = (size_t)row * E_;
    float4 av = *(const float4*)&a[base + t * 4];
    float4 rv = *(const float4*)&r[base + t * 4];
    float v0 = av.x + rv.x, v1 = av.y + rv.y, v2 = av.z + rv.z, v3 = av.w + rv.w;
    float sum = v0 + v1 + v2 + v3;
    float sq = v0 * v0 + v1 * v1 + v2 * v2 + v3 * v3;
#pragma unroll
    for (int off = 16; off; off >>= 1) {
        sum += __shfl_xor_sync(0xffffffffu, sum, off);
        sq  += __shfl_xor_sync(0xffffffffu, sq, off);
    }
    __shared__ float ss[8], sq2[8], stat[2];
    int w = t >> 5;
    if ((t & 31) == 0) { ss[w] = sum; sq2[w] = sq; }
    __syncthreads();
    if (t == 0) {
        float S1 = 0.f, S2 = 0.f;
        for (int i = 0; i < 8; i++) { S1 += ss[i]; S2 += sq2[i]; }
        float mean = S1 * (1.0f / E_);
        float var = S2 * (1.0f / E_) - mean * mean;
        stat[0] = mean;
        stat[1] = rsqrtf(var + 1e-5f);
    }
    __syncthreads();
    float mean = stat[0], rstd = stat[1];
    float4 gv = *(const float4*)&g[t * 4];
    float4 bv = *(const float4*)&be[t * 4];
    float o[4];
    o[0] = (v0 - mean) * rstd * gv.x + bv.x;
    o[1] = (v1 - mean) * rstd * gv.y + bv.y;
    o[2] = (v2 - mean) * rstd * gv.z + bv.z;
    o[3] = (v3 - mean) * rstd * gv.w + bv.w;
    *(float4*)&out[base + t * 4] = make_float4(o[0], o[1], o[2], o[3]);
    if (oh) {
        uint2 ho;
        ho.x = pack_h2(o[0], o[1]);
        ho.y = pack_h2(o[2], o[3]);
        *(uint2*)&oh[base + t * 4] = ho;
    }
}

// ---------------- launch ---------------------------------------------------------
extern "C" void kernel_launch(void* const* d_in, const int* in_sizes, int n_in,
                              void* d_out, int out_size)
{
    (void)in_sizes; (void)n_in; (void)out_size;
    const float* x    = (const float*)d_in[0];
    const float* ipw  = (const float*)d_in[1];
    const float* ipb  = (const float*)d_in[2];
    const float* opw  = (const float*)d_in[3];
    const float* opb  = (const float*)d_in[4];
    const float* ln1g = (const float*)d_in[5];
    const float* ln1b = (const float*)d_in[6];
    const float* w1   = (const float*)d_in[7];
    const float* b1   = (const float*)d_in[8];
    const float* w2   = (const float*)d_in[9];
    const float* b2   = (const float*)d_in[10];
    const float* ln2g = (const float*)d_in[11];
    const float* ln2b = (const float*)d_in[12];
    float* out = (float*)d_out;

    float *vb, *tmp, *x1, *qk;
    cudaGetSymbolAddress((void**)&vb,  g_v);
    cudaGetSymbolAddress((void**)&tmp, g_tmp);
    cudaGetSymbolAddress((void**)&x1,  g_x1);
    cudaGetSymbolAddress((void**)&qk,  g_qk);

    __half *a1h, *a2h, *x1h, *hh, *wih, *woh, *w1h, *w2h;
    cudaGetSymbolAddress((void**)&a1h, g_a1h);
    cudaGetSymbolAddress((void**)&a2h, g_a2h);
    cudaGetSymbolAddress((void**)&x1h, g_x1h);
    cudaGetSymbolAddress((void**)&hh,  g_hh);
    cudaGetSymbolAddress((void**)&wih, g_wih); cudaGetSymbolAddress((void**)&woh, g_woh);
    cudaGetSymbolAddress((void**)&w1h, g_w1h); cudaGetSymbolAddress((void**)&w2h, g_w2h);

    int attn_smem = 4 * 64 * SP * (int)sizeof(float);
    cudaFuncSetAttribute(attn_kernel,
                         cudaFuncAttributeMaxDynamicSharedMemorySize, attn_smem);
    cudaFuncSetAttribute(gemm_mma_kernel<0,0>,
                         cudaFuncAttributeMaxDynamicSharedMemorySize, GEMM_SMEM);
    cudaFuncSetAttribute(gemm_mma_kernel<1,1>,
                         cudaFuncAttributeMaxDynamicSharedMemorySize, GEMM_SMEM);

    // launch order keeps the fused Q|K GEMM at index 5 (ncu -s 5 -c 1 profiles it)
    rope_conv_kernel<<<BS, 256>>>(x, a1h);                             // 0
    conv_kernel<<<(BS * E_) / 1024, 256>>>(x, a2h);                    // 1
    conv_kernel<<<(3 * E_ * E_) / 1024, 256>>>(ipw, wih);              // 2
    conv_kernel<<<(E_ * E_) / 1024, 256>>>(opw, woh);                  // 3
    conv_kernel<<<(FF * E_) / 1024, 256>>>(w1, w1h);                   // 4

    // 5: fused Q|K GEMM (N=2048)  <-- profiled launch
    gemm_mma_kernel<0,0><<<dim3(16, 64), 256, GEMM_SMEM>>>(
        a1h, wih, ipb, qk, nullptr, BS, 2 * E_, E_);

    conv_kernel<<<(FF * E_) / 1024, 256>>>(w2, w2h);                   // 6

    // V GEMM
    gemm_mma_kernel<0,0><<<dim3(8, 64), 256, GEMM_SMEM>>>(
        a2h, wih + (size_t)2*E_*E_, ipb + 2 * E_, vb, nullptr, BS, E_, E_);

    // attention -> ctx fp16 (reuses a2h)
    attn_kernel<<<dim3(SS / 64, NH, BB), 256, attn_smem>>>(
        qk, qk + E_, vb, 2 * E_, a2h);

    // out-proj, residual + LN1 -> x1 (+ fp16 x1h)
    gemm_mma_kernel<0,0><<<dim3(8, 64), 256, GEMM_SMEM>>>(
        a2h, woh, opb, tmp, nullptr, BS, E_, E_);
    add_ln_kernel<<<BS, 256>>>(x, tmp, ln1g, ln1b, x1, x1h);

    // FFN
    gemm_mma_kernel<1,1><<<dim3(32, 64), 256, GEMM_SMEM>>>(
        x1h, w1h, b1, nullptr, hh, BS, FF, E_);
    gemm_mma_kernel<0,0><<<dim3(8, 64), 256, GEMM_SMEM>>>(
        hh, w2h, b2, tmp, nullptr, BS, E_, FF);
    add_ln_kernel<<<BS, 256>>>(x1, tmp, ln2g, ln2b, out, nullptr);
}

// round 8
// speedup vs baseline: 7.3706x; 1.9580x over previous
#include <cuda_runtime.h>
#include <cuda_fp16.h>
#include <math.h>
#include <stdint.h>

#define E_   1024
#define NH   16
#define HD   64
#define WIN  256
#define BB   8
#define SS   1024
#define BS   (BB*SS)
#define FF   4096

// ---------------- scratch ------------------------------------------------------
__device__ float g_tmp[BS*E_];
__device__ float g_x1[BS*E_];

__device__ __half g_a1h[BS*E_];                  // roped input (fp16)
__device__ __half g_a2h[BS*E_];                  // x -> later ctx (fp16, reused)
__device__ __half g_x1h[BS*E_];                  // x1 (fp16)
__device__ __half g_hh[(size_t)BS*FF];           // GELU(ffn1) (fp16)
__device__ __half g_qkh[(size_t)BS*2*E_];        // fused Q|K (fp16)
__device__ __half g_vh[BS*E_];                   // V (fp16)
__device__ __half g_wih[3*E_*E_];
__device__ __half g_woh[E_*E_];
__device__ __half g_w1h[FF*E_];
__device__ __half g_w2h[FF*E_];

// ---------------- helpers -------------------------------------------------------
__device__ __forceinline__ uint32_t smem_u32(const void* p) {
    uint32_t a;
    asm("{ .reg .u64 t; cvta.to.shared.u64 t, %1; cvt.u32.u64 %0, t; }" : "=r"(a) : "l"(p));
    return a;
}
__device__ __forceinline__ void cp16(uint32_t dst, const void* src) {
    asm volatile("cp.async.cg.shared.global [%0], [%1], 16;" :: "r"(dst), "l"(src));
}
__device__ __forceinline__ void cp_commit() { asm volatile("cp.async.commit_group;"); }
__device__ __forceinline__ void cp_wait2()  { asm volatile("cp.async.wait_group 2;" ::: "memory"); }
__device__ __forceinline__ void ldm_x4(uint32_t addr, uint32_t& r0, uint32_t& r1,
                                       uint32_t& r2, uint32_t& r3) {
    asm volatile("ldmatrix.sync.aligned.m8n8.x4.shared.b16 {%0,%1,%2,%3}, [%4];"
                 : "=r"(r0), "=r"(r1), "=r"(r2), "=r"(r3) : "r"(addr));
}
__device__ __forceinline__ void ldm_x4t(uint32_t addr, uint32_t& r0, uint32_t& r1,
                                        uint32_t& r2, uint32_t& r3) {
    asm volatile("ldmatrix.sync.aligned.m8n8.x4.trans.shared.b16 {%0,%1,%2,%3}, [%4];"
                 : "=r"(r0), "=r"(r1), "=r"(r2), "=r"(r3) : "r"(addr));
}
__device__ __forceinline__ void mma16816(float* c, const uint32_t* a, const uint32_t* b) {
    asm volatile(
        "mma.sync.aligned.m16n8k16.row.col.f32.f16.f16.f32 "
        "{%0,%1,%2,%3}, {%4,%5,%6,%7}, {%8,%9}, {%0,%1,%2,%3};"
        : "+f"(c[0]), "+f"(c[1]), "+f"(c[2]), "+f"(c[3])
        : "r"(a[0]), "r"(a[1]), "r"(a[2]), "r"(a[3]), "r"(b[0]), "r"(b[1]));
}
__device__ __forceinline__ uint32_t pack_h2(float a, float b) {
    __half2 h = __floats2half2_rn(a, b);
    return *(uint32_t*)&h;
}

// ---------------- convert fp32 -> fp16 -------------------------------------------
__global__ __launch_bounds__(256) void conv_kernel(const float* __restrict__ src,
                                                   __half* __restrict__ hi)
{
    size_t i = ((size_t)blockIdx.x * 256 + threadIdx.x) * 4;
    float4 v = *(const float4*)&src[i];
    uint2 ho;
    ho.x = pack_h2(v.x, v.y);
    ho.y = pack_h2(v.z, v.w);
    *(uint2*)&hi[i] = ho;
}

// ---------------- RoPE on raw x -> fp16 ------------------------------------------
__global__ __launch_bounds__(256) void rope_conv_kernel(const float* __restrict__ x,
                                                        __half* __restrict__ hi)
{
    int tok = blockIdx.x;
    float pos = (float)(tok & (SS - 1));
    int base = tok * E_ + threadIdx.x * 4;
    int d = (threadIdx.x * 4) & (HD - 1);
    const float* xp = &x[base];
    float4 xv = *(const float4*)xp;
    float res[4];
    const float LOG2_10000 = 13.287712379549449f;
#pragma unroll
    for (int i = 0; i < 4; i++) {
        int dd = d + i;
        int j = (dd < 32) ? dd : dd - 32;
        float fr = exp2f(-(float)j * (2.0f / 64.0f) * LOG2_10000);
        float ang = pos * fr;
        float s, c;
        sincosf(ang, &s, &c);
        float v = ((const float*)&xv)[i];
        float other = (dd < 32) ? -xp[i + 32] : xp[i - 32];
        res[i] = v * c + other * s;
    }
    uint2 ho;
    ho.x = pack_h2(res[0], res[1]);
    ho.y = pack_h2(res[2], res[3]);
    *(uint2*)&hi[base] = ho;
}

// ---------------- HMMA fp16 GEMM: C[M,N] = A[M,K] @ W[N,K]^T + bias --------------
#define STG 4
#define GEMM_SMEM (STG * 16384)

template<int ACT, int MODE>
__global__ __launch_bounds__(256, 2) void gemm_mma_kernel(
    const __half* __restrict__ Ah, const __half* __restrict__ Bh,
    const float* __restrict__ bias, float* __restrict__ C,
    __half* __restrict__ Ch,
    int M, int N, int K)
{
    extern __shared__ __align__(16) char smc[];
    uint32_t sbase = smem_u32(smc);
    const uint32_t BOFF = STG * 8192;

    int t = threadIdx.x;
    int lane = t & 31, wid = t >> 5;
    int warp_m = wid & 3, warp_n = wid >> 2;
    int m0 = blockIdx.y * 128;
    int n0 = blockIdx.x * 128;

    uint32_t aOff[2];
    size_t   aG[2], bG[2];
#pragma unroll
    for (int i = 0; i < 2; i++) {
        int idx = t + i * 256;
        int row = idx >> 2, ch = idx & 3;
        uint32_t swz = (uint32_t)(ch ^ ((row >> 1) & 3));
        aOff[i] = (uint32_t)(row * 64) + swz * 16;
        aG[i] = (size_t)(m0 + row) * K + ch * 8;
        bG[i] = (size_t)(n0 + row) * K + ch * 8;
    }

    uint32_t aRow64[2]; int aRswz[2];
#pragma unroll
    for (int ti = 0; ti < 2; ti++) {
        int row = warp_m * 32 + ti * 16 + (lane & 15);
        aRow64[ti] = (uint32_t)(row * 64);
        aRswz[ti] = (row >> 1) & 3;
    }
    int aChunkBase = lane >> 4;
    uint32_t bRow64[4]; int bRswz[4];
#pragma unroll
    for (int j2 = 0; j2 < 4; j2++) {
        int row = warp_n * 64 + j2 * 16 + ((lane >> 4) << 3) + (lane & 7);
        bRow64[j2] = (uint32_t)(row * 64);
        bRswz[j2] = (row >> 1) & 3;
    }
    int bChunkBase = (lane >> 3) & 1;

    float acc[2][8][4];
#pragma unroll
    for (int mi = 0; mi < 2; mi++)
#pragma unroll
        for (int nj = 0; nj < 8; nj++)
#pragma unroll
            for (int r = 0; r < 4; r++) acc[mi][nj][r] = 0.f;

    int NC = K >> 5;

#pragma unroll
    for (int p = 0; p < 3; p++) {
        size_t ko = (size_t)p * 32;
        uint32_t sa = sbase + (uint32_t)p * 8192;
        uint32_t sb = sbase + BOFF + (uint32_t)p * 8192;
#pragma unroll
        for (int i = 0; i < 2; i++) cp16(sa + aOff[i], Ah + aG[i] + ko);
#pragma unroll
        for (int i = 0; i < 2; i++) cp16(sb + aOff[i], Bh + bG[i] + ko);
        cp_commit();
    }

    for (int c = 0; c < NC; c++) {
        cp_wait2();
        __syncthreads();

        if (c + 3 < NC) {
            size_t ko = (size_t)(c + 3) * 32;
            uint32_t st = (uint32_t)((c + 3) & (STG - 1));
            uint32_t sa = sbase + st * 8192;
            uint32_t sb = sbase + BOFF + st * 8192;
#pragma unroll
            for (int i = 0; i < 2; i++) cp16(sa + aOff[i], Ah + aG[i] + ko);
#pragma unroll
            for (int i = 0; i < 2; i++) cp16(sb + aOff[i], Bh + bG[i] + ko);
        }
        cp_commit();

        uint32_t sa = sbase + (uint32_t)(c & (STG - 1)) * 8192;
        uint32_t sb = sbase + BOFF + (uint32_t)(c & (STG - 1)) * 8192;
#pragma unroll
        for (int kstep = 0; kstep < 2; kstep++) {
            uint32_t a[2][4], b[4][4];
#pragma unroll
            for (int ti = 0; ti < 2; ti++) {
                int ch = kstep * 2 + aChunkBase;
                uint32_t addr = sa + aRow64[ti] + (uint32_t)((ch ^ aRswz[ti]) * 16);
                ldm_x4(addr, a[ti][0], a[ti][1], a[ti][2], a[ti][3]);
            }
#pragma unroll
            for (int j2 = 0; j2 < 4; j2++) {
                int ch = kstep * 2 + bChunkBase;
                uint32_t addr = sb + bRow64[j2] + (uint32_t)((ch ^ bRswz[j2]) * 16);
                ldm_x4(addr, b[j2][0], b[j2][1], b[j2][2], b[j2][3]);
            }
#pragma unroll
            for (int mi = 0; mi < 2; mi++)
#pragma unroll
                for (int nj = 0; nj < 8; nj++)
                    mma16816(acc[mi][nj], a[mi], &b[nj >> 1][(nj & 1) * 2]);
        }
    }

    int tq = lane >> 2, tr = lane & 3;
#pragma unroll
    for (int mi = 0; mi < 2; mi++) {
#pragma unroll
        for (int nj = 0; nj < 8; nj++) {
            int row0 = m0 + warp_m * 32 + mi * 16 + tq;
            int col = n0 + warp_n * 64 + nj * 8 + tr * 2;
            float b0 = __ldg(&bias[col]), b1 = __ldg(&bias[col + 1]);
            float v0 = acc[mi][nj][0] + b0, v1 = acc[mi][nj][1] + b1;
            float v2 = acc[mi][nj][2] + b0, v3 = acc[mi][nj][3] + b1;
            if (ACT) {
                v0 = 0.5f * v0 * (1.0f + erff(v0 * 0.70710678118654752f));
                v1 = 0.5f * v1 * (1.0f + erff(v1 * 0.70710678118654752f));
                v2 = 0.5f * v2 * (1.0f + erff(v2 * 0.70710678118654752f));
                v3 = 0.5f * v3 * (1.0f + erff(v3 * 0.70710678118654752f));
            }
            if (MODE == 0) {
                *(float2*)&C[(size_t)row0 * N + col] = make_float2(v0, v1);
                *(float2*)&C[(size_t)(row0 + 8) * N + col] = make_float2(v2, v3);
            } else {
                *(uint32_t*)&Ch[(size_t)row0 * N + col] = pack_h2(v0, v1);
                *(uint32_t*)&Ch[(size_t)(row0 + 8) * N + col] = pack_h2(v2, v3);
            }
        }
    }
}

// ---------------- tensor-core flash attention (fp16 in, fp16 out) ----------------
// 128 threads = 4 warps. Warp w handles q-rows [q0+16w, q0+16w+16).
// smem tiles 64x64 fp16, row=128B=8 chunks, swizzle: chunk ^ (row&7).
__global__ __launch_bounds__(128) void attn_mma_kernel(
    const __half* __restrict__ qk,   // [BS][2E] : Q | K
    const __half* __restrict__ v,    // [BS][E]
    __half* __restrict__ ch)         // ctx [BS][E]
{
    __shared__ __align__(16) __half q_s[64 * 64];
    __shared__ __align__(16) __half k_s[64 * 64];
    __shared__ __align__(16) __half v_s[64 * 64];

    int b = blockIdx.z, h = blockIdx.y;
    int q0 = blockIdx.x * 64;
    int t = threadIdx.x;
    int lane = t & 31, w = t >> 5;
    uint32_t sq = smem_u32(q_s), sk = smem_u32(k_s), sv = smem_u32(v_s);

    // ---- load Q tile (swizzled)
#pragma unroll
    for (int i = 0; i < 4; i++) {
        int idx = t + i * 128;
        int r = idx >> 3, c = idx & 7;
        *(uint4*)((char*)q_s + r * 128 + ((c ^ (r & 7)) * 16)) =
            *(const uint4*)&qk[(size_t)(b * SS + q0 + r) * (2 * E_) + h * HD + c * 8];
    }
    __syncthreads();

    // ---- Q fragments (persist across k-blocks)
    uint32_t qa[4][4];
#pragma unroll
    for (int kc = 0; kc < 4; kc++) {
        int m = lane >> 3;
        int rr = w * 16 + (lane & 7) + ((m & 1) ? 8 : 0);
        int cc = kc * 2 + (m >> 1);
        uint32_t addr = sq + (uint32_t)(rr * 128 + ((cc ^ (rr & 7)) * 16));
        ldm_x4(addr, qa[kc][0], qa[kc][1], qa[kc][2], qa[kc][3]);
    }

    float o[8][4];
#pragma unroll
    for (int d = 0; d < 8; d++)
#pragma unroll
        for (int r = 0; r < 4; r++) o[d][r] = 0.f;
    float mrow[2] = {-1e30f, -1e30f};
    float lsum[2] = {0.f, 0.f};

    int kstart = q0 - WIN; if (kstart < 0) kstart = 0;
    int kend = q0 + 64 + WIN; if (kend > SS) kend = SS;
    const float scale = 0.125f;
    int tq = lane >> 2, tr = lane & 3;

    for (int kb = kstart; kb < kend; kb += 64) {
        __syncthreads();
        // load K,V tiles (swizzled)
#pragma unroll
        for (int i = 0; i < 4; i++) {
            int idx = t + i * 128;
            int r = idx >> 3, c = idx & 7;
            uint32_t so = (uint32_t)(r * 128 + ((c ^ (r & 7)) * 16));
            *(uint4*)((char*)k_s + so) =
                *(const uint4*)&qk[(size_t)(b * SS + kb + r) * (2 * E_) + E_ + h * HD + c * 8];
            *(uint4*)((char*)v_s + so) =
                *(const uint4*)&v[(size_t)(b * SS + kb + r) * E_ + h * HD + c * 8];
        }
        __syncthreads();

        // ---- scores S = Q K^T (8 n-tiles of 8 keys)
        float s[8][4];
#pragma unroll
        for (int j = 0; j < 8; j++)
#pragma unroll
            for (int r = 0; r < 4; r++) s[j][r] = 0.f;
#pragma unroll
        for (int kc = 0; kc < 4; kc++) {
#pragma unroll
            for (int j2 = 0; j2 < 4; j2++) {
                int m = lane >> 3;
                int rr = j2 * 16 + (lane & 7) + ((m >= 2) ? 8 : 0);
                int cc = kc * 2 + (m & 1);
                uint32_t addr = sk + (uint32_t)(rr * 128 + ((cc ^ (rr & 7)) * 16));
                uint32_t b0, b1, b2, b3;
                ldm_x4(addr, b0, b1, b2, b3);
                uint32_t bj[2] = {b0, b1}, bj1[2] = {b2, b3};
                mma16816(s[2 * j2],     qa[kc], bj);
                mma16816(s[2 * j2 + 1], qa[kc], bj1);
            }
        }

        // ---- mask + online softmax (rows tq and tq+8)
#pragma unroll
        for (int e = 0; e < 2; e++) {
            int qi = q0 + w * 16 + tq + e * 8;
            float rmax = -1e30f;
#pragma unroll
            for (int j = 0; j < 8; j++) {
#pragma unroll
                for (int u = 0; u < 2; u++) {
                    int col = kb + j * 8 + tr * 2 + u;
                    int diff = qi - col;
                    bool ok = (diff <= WIN) && (diff >= -WIN);
                    float val = ok ? s[j][e * 2 + u] * scale : -1e30f;
                    s[j][e * 2 + u] = val;
                    rmax = fmaxf(rmax, val);
                }
            }
            rmax = fmaxf(rmax, __shfl_xor_sync(0xffffffffu, rmax, 1));
            rmax = fmaxf(rmax, __shfl_xor_sync(0xffffffffu, rmax, 2));
            float mnew = fmaxf(mrow[e], rmax);
            float corr = expf(mrow[e] - mnew);
            float rsum = 0.f;
#pragma unroll
            for (int j = 0; j < 8; j++) {
#pragma unroll
                for (int u = 0; u < 2; u++) {
                    float p = expf(s[j][e * 2 + u] - mnew);
                    s[j][e * 2 + u] = p;
                    rsum += p;
                }
            }
            rsum += __shfl_xor_sync(0xffffffffu, rsum, 1);
            rsum += __shfl_xor_sync(0xffffffffu, rsum, 2);
            mrow[e] = mnew;
            lsum[e] = lsum[e] * corr + rsum;
#pragma unroll
            for (int d = 0; d < 8; d++) {
                o[d][e * 2] *= corr;
                o[d][e * 2 + 1] *= corr;
            }
        }

        // ---- O += P V   (P fragments straight from score registers)
#pragma unroll
        for (int kc = 0; kc < 4; kc++) {
            uint32_t pa[4];
            pa[0] = pack_h2(s[2 * kc][0],     s[2 * kc][1]);
            pa[1] = pack_h2(s[2 * kc][2],     s[2 * kc][3]);
            pa[2] = pack_h2(s[2 * kc + 1][0], s[2 * kc + 1][1]);
            pa[3] = pack_h2(s[2 * kc + 1][2], s[2 * kc + 1][3]);
#pragma unroll
            for (int d2 = 0; d2 < 4; d2++) {
                int m = lane >> 3;
                int rr = kc * 16 + (lane & 7) + ((m & 1) ? 8 : 0);
                int cc = 2 * d2 + (m >> 1);
                uint32_t addr = sv + (uint32_t)(rr * 128 + ((cc ^ (rr & 7)) * 16));
                uint32_t b0, b1, b2, b3;
                ldm_x4t(addr, b0, b1, b2, b3);
                uint32_t bd[2] = {b0, b1}, bd1[2] = {b2, b3};
                mma16816(o[2 * d2],     pa, bd);
                mma16816(o[2 * d2 + 1], pa, bd1);
            }
        }
    }

    // ---- epilogue: scale by 1/lsum, write fp16 ctx
    float inv0 = 1.f / lsum[0], inv1 = 1.f / lsum[1];
#pragma unroll
    for (int d = 0; d < 8; d++) {
        int row0 = q0 + w * 16 + tq;
        int col = h * HD + d * 8 + tr * 2;
        *(uint32_t*)&ch[(size_t)(b * SS + row0) * E_ + col] =
            pack_h2(o[d][0] * inv0, o[d][1] * inv0);
        *(uint32_t*)&ch[(size_t)(b * SS + row0 + 8) * E_ + col] =
            pack_h2(o[d][2] * inv1, o[d][3] * inv1);
    }
}

// ---------------- residual add + LayerNorm (optional fused fp16 out) -------------
__global__ __launch_bounds__(256) void add_ln_kernel(
    const float* __restrict__ a, const float* __restrict__ r,
    const float* __restrict__ g, const float* __restrict__ be,
    float* __restrict__ out, __half* __restrict__ oh)
{
    int row = blockIdx.x;
    int t = threadIdx.x;
    size_t base = (size_t)row * E_;
    float4 av = *(const float4*)&a[base + t * 4];
    float4 rv = *(const float4*)&r[base + t * 4];
    float v0 = av.x + rv.x, v1 = av.y + rv.y, v2 = av.z + rv.z, v3 = av.w + rv.w;
    float sum = v0 + v1 + v2 + v3;
    float sq = v0 * v0 + v1 * v1 + v2 * v2 + v3 * v3;
#pragma unroll
    for (int off = 16; off; off >>= 1) {
        sum += __shfl_xor_sync(0xffffffffu, sum, off);
        sq  += __shfl_xor_sync(0xffffffffu, sq, off);
    }
    __shared__ float ss[8], sq2[8], stat[2];
    int w = t >> 5;
    if ((t & 31) == 0) { ss[w] = sum; sq2[w] = sq; }
    __syncthreads();
    if (t == 0) {
        float S1 = 0.f, S2 = 0.f;
        for (int i = 0; i < 8; i++) { S1 += ss[i]; S2 += sq2[i]; }
        float mean = S1 * (1.0f / E_);
        float var = S2 * (1.0f / E_) - mean * mean;
        stat[0] = mean;
        stat[1] = rsqrtf(var + 1e-5f);
    }
    __syncthreads();
    float mean = stat[0], rstd = stat[1];
    float4 gv = *(const float4*)&g[t * 4];
    float4 bv = *(const float4*)&be[t * 4];
    float o[4];
    o[0] = (v0 - mean) * rstd * gv.x + bv.x;
    o[1] = (v1 - mean) * rstd * gv.y + bv.y;
    o[2] = (v2 - mean) * rstd * gv.z + bv.z;
    o[3] = (v3 - mean) * rstd * gv.w + bv.w;
    *(float4*)&out[base + t * 4] = make_float4(o[0], o[1], o[2], o[3]);
    if (oh) {
        uint2 ho;
        ho.x = pack_h2(o[0], o[1]);
        ho.y = pack_h2(o[2], o[3]);
        *(uint2*)&oh[base + t * 4] = ho;
    }
}

// ---------------- launch ---------------------------------------------------------
extern "C" void kernel_launch(void* const* d_in, const int* in_sizes, int n_in,
                              void* d_out, int out_size)
{
    (void)in_sizes; (void)n_in; (void)out_size;
    const float* x    = (const float*)d_in[0];
    const float* ipw  = (const float*)d_in[1];
    const float* ipb  = (const float*)d_in[2];
    const float* opw  = (const float*)d_in[3];
    const float* opb  = (const float*)d_in[4];
    const float* ln1g = (const float*)d_in[5];
    const float* ln1b = (const float*)d_in[6];
    const float* w1   = (const float*)d_in[7];
    const float* b1   = (const float*)d_in[8];
    const float* w2   = (const float*)d_in[9];
    const float* b2   = (const float*)d_in[10];
    const float* ln2g = (const float*)d_in[11];
    const float* ln2b = (const float*)d_in[12];
    float* out = (float*)d_out;

    float *tmp, *x1;
    cudaGetSymbolAddress((void**)&tmp, g_tmp);
    cudaGetSymbolAddress((void**)&x1,  g_x1);

    __half *a1h, *a2h, *x1h, *hh, *qkh, *vh, *wih, *woh, *w1h, *w2h;
    cudaGetSymbolAddress((void**)&a1h, g_a1h);
    cudaGetSymbolAddress((void**)&a2h, g_a2h);
    cudaGetSymbolAddress((void**)&x1h, g_x1h);
    cudaGetSymbolAddress((void**)&hh,  g_hh);
    cudaGetSymbolAddress((void**)&qkh, g_qkh);
    cudaGetSymbolAddress((void**)&vh,  g_vh);
    cudaGetSymbolAddress((void**)&wih, g_wih); cudaGetSymbolAddress((void**)&woh, g_woh);
    cudaGetSymbolAddress((void**)&w1h, g_w1h); cudaGetSymbolAddress((void**)&w2h, g_w2h);

    cudaFuncSetAttribute(gemm_mma_kernel<0,0>,
                         cudaFuncAttributeMaxDynamicSharedMemorySize, GEMM_SMEM);
    cudaFuncSetAttribute(gemm_mma_kernel<0,1>,
                         cudaFuncAttributeMaxDynamicSharedMemorySize, GEMM_SMEM);
    cudaFuncSetAttribute(gemm_mma_kernel<1,1>,
                         cudaFuncAttributeMaxDynamicSharedMemorySize, GEMM_SMEM);

    // launch order keeps the fused Q|K GEMM at index 5 (ncu -s 5 -c 1 profiles it)
    rope_conv_kernel<<<BS, 256>>>(x, a1h);                             // 0
    conv_kernel<<<(BS * E_) / 1024, 256>>>(x, a2h);                    // 1
    conv_kernel<<<(3 * E_ * E_) / 1024, 256>>>(ipw, wih);              // 2
    conv_kernel<<<(E_ * E_) / 1024, 256>>>(opw, woh);                  // 3
    conv_kernel<<<(FF * E_) / 1024, 256>>>(w1, w1h);                   // 4

    // 5: fused Q|K GEMM (N=2048, fp16 out)  <-- profiled launch
    gemm_mma_kernel<0,1><<<dim3(16, 64), 256, GEMM_SMEM>>>(
        a1h, wih, ipb, nullptr, qkh, BS, 2 * E_, E_);

    conv_kernel<<<(FF * E_) / 1024, 256>>>(w2, w2h);                   // 6

    // V GEMM (fp16 out)
    gemm_mma_kernel<0,1><<<dim3(8, 64), 256, GEMM_SMEM>>>(
        a2h, wih + (size_t)2*E_*E_, ipb + 2 * E_, nullptr, vh, BS, E_, E_);

    // tensor-core attention -> ctx fp16 (reuses a2h)
    attn_mma_kernel<<<dim3(SS / 64, NH, BB), 128>>>(qkh, vh, a2h);

    // out-proj, residual + LN1 -> x1 (+ fp16 x1h)
    gemm_mma_kernel<0,0><<<dim3(8, 64), 256, GEMM_SMEM>>>(
        a2h, woh, opb, tmp, nullptr, BS, E_, E_);
    add_ln_kernel<<<BS, 256>>>(x, tmp, ln1g, ln1b, x1, x1h);

    // FFN
    gemm_mma_kernel<1,1><<<dim3(32, 64), 256, GEMM_SMEM>>>(
        x1h, w1h, b1, nullptr, hh, BS, FF, E_);
    gemm_mma_kernel<0,0><<<dim3(8, 64), 256, GEMM_SMEM>>>(
        hh, w2h, b2, tmp, nullptr, BS, E_, FF);
    add_ln_kernel<<<BS, 256>>>(x1, tmp, ln2g, ln2b, out, nullptr);
}

// round 9
// speedup vs baseline: 7.5780x; 1.0281x over previous
#include <cuda_runtime.h>
#include <cuda_fp16.h>
#include <math.h>
#include <stdint.h>

#define E_   1024
#define NH   16
#define HD   64
#define WIN  256
#define BB   8
#define SS   1024
#define BS   (BB*SS)
#define FF   4096

// ---------------- scratch ------------------------------------------------------
__device__ float g_tmp[BS*E_];
__device__ float g_x1[BS*E_];

__device__ __half g_a1h[BS*E_];                  // roped input (fp16)
__device__ __half g_a2h[BS*E_];                  // x -> later ctx (fp16, reused)
__device__ __half g_x1h[BS*E_];                  // x1 (fp16)
__device__ __half g_hh[(size_t)BS*FF];           // GELU(ffn1) (fp16)
__device__ __half g_qkh[(size_t)BS*2*E_];        // fused Q|K (fp16)
__device__ __half g_vh[BS*E_];                   // V (fp16)
__device__ __half g_wih[3*E_*E_];
__device__ __half g_woh[E_*E_];
__device__ __half g_w1h[FF*E_];
__device__ __half g_w2h[FF*E_];

// ---------------- streams/events (created at load time, before mem checkpoints) --
struct StreamPack {
    cudaStream_t s2;
    cudaEvent_t eStart, eR, eWih, eV, eW2;
    StreamPack() {
        cudaStreamCreateWithFlags(&s2, cudaStreamNonBlocking);
        cudaEventCreateWithFlags(&eStart, cudaEventDisableTiming);
        cudaEventCreateWithFlags(&eR,     cudaEventDisableTiming);
        cudaEventCreateWithFlags(&eWih,   cudaEventDisableTiming);
        cudaEventCreateWithFlags(&eV,     cudaEventDisableTiming);
        cudaEventCreateWithFlags(&eW2,    cudaEventDisableTiming);
    }
};
static StreamPack g_sp;

// ---------------- helpers -------------------------------------------------------
__device__ __forceinline__ uint32_t smem_u32(const void* p) {
    uint32_t a;
    asm("{ .reg .u64 t; cvta.to.shared.u64 t, %1; cvt.u32.u64 %0, t; }" : "=r"(a) : "l"(p));
    return a;
}
__device__ __forceinline__ void cp16(uint32_t dst, const void* src) {
    asm volatile("cp.async.cg.shared.global [%0], [%1], 16;" :: "r"(dst), "l"(src));
}
__device__ __forceinline__ void cp_commit() { asm volatile("cp.async.commit_group;"); }
__device__ __forceinline__ void cp_wait2()  { asm volatile("cp.async.wait_group 2;" ::: "memory"); }
__device__ __forceinline__ void ldm_x4(uint32_t addr, uint32_t& r0, uint32_t& r1,
                                       uint32_t& r2, uint32_t& r3) {
    asm volatile("ldmatrix.sync.aligned.m8n8.x4.shared.b16 {%0,%1,%2,%3}, [%4];"
                 : "=r"(r0), "=r"(r1), "=r"(r2), "=r"(r3) : "r"(addr));
}
__device__ __forceinline__ void ldm_x4t(uint32_t addr, uint32_t& r0, uint32_t& r1,
                                        uint32_t& r2, uint32_t& r3) {
    asm volatile("ldmatrix.sync.aligned.m8n8.x4.trans.shared.b16 {%0,%1,%2,%3}, [%4];"
                 : "=r"(r0), "=r"(r1), "=r"(r2), "=r"(r3) : "r"(addr));
}
__device__ __forceinline__ void mma16816(float* c, const uint32_t* a, const uint32_t* b) {
    asm volatile(
        "mma.sync.aligned.m16n8k16.row.col.f32.f16.f16.f32 "
        "{%0,%1,%2,%3}, {%4,%5,%6,%7}, {%8,%9}, {%0,%1,%2,%3};"
        : "+f"(c[0]), "+f"(c[1]), "+f"(c[2]), "+f"(c[3])
        : "r"(a[0]), "r"(a[1]), "r"(a[2]), "r"(a[3]), "r"(b[0]), "r"(b[1]));
}
__device__ __forceinline__ uint32_t pack_h2(float a, float b) {
    __half2 h = __floats2half2_rn(a, b);
    return *(uint32_t*)&h;
}

// ---------------- convert fp32 -> fp16 -------------------------------------------
__global__ __launch_bounds__(256) void conv_kernel(const float* __restrict__ src,
                                                   __half* __restrict__ hi)
{
    size_t i = ((size_t)blockIdx.x * 256 + threadIdx.x) * 4;
    float4 v = *(const float4*)&src[i];
    uint2 ho;
    ho.x = pack_h2(v.x, v.y);
    ho.y = pack_h2(v.z, v.w);
    *(uint2*)&hi[i] = ho;
}

// ---------------- RoPE on raw x -> fp16 roped + fp16 plain -----------------------
__global__ __launch_bounds__(256) void rope_conv_kernel(const float* __restrict__ x,
                                                        __half* __restrict__ hi,
                                                        __half* __restrict__ xh)
{
    int tok = blockIdx.x;
    float pos = (float)(tok & (SS - 1));
    int base = tok * E_ + threadIdx.x * 4;
    int d = (threadIdx.x * 4) & (HD - 1);
    const float* xp = &x[base];
    float4 xv = *(const float4*)xp;
    float res[4];
    const float LOG2_10000 = 13.287712379549449f;
#pragma unroll
    for (int i = 0; i < 4; i++) {
        int dd = d + i;
        int j = (dd < 32) ? dd : dd - 32;
        float fr = exp2f(-(float)j * (2.0f / 64.0f) * LOG2_10000);
        float ang = pos * fr;
        float s, c;
        sincosf(ang, &s, &c);
        float v = ((const float*)&xv)[i];
        float other = (dd < 32) ? -xp[i + 32] : xp[i - 32];
        res[i] = v * c + other * s;
    }
    uint2 ho, xo;
    ho.x = pack_h2(res[0], res[1]);
    ho.y = pack_h2(res[2], res[3]);
    xo.x = pack_h2(xv.x, xv.y);
    xo.y = pack_h2(xv.z, xv.w);
    *(uint2*)&hi[base] = ho;
    *(uint2*)&xh[base] = xo;
}

// ---------------- HMMA fp16 GEMM: C[M,N] = A[M,K] @ W[N,K]^T + bias --------------
#define STG 4
#define GEMM_SMEM (STG * 16384)

template<int ACT, int MODE>
__global__ __launch_bounds__(256, 2) void gemm_mma_kernel(
    const __half* __restrict__ Ah, const __half* __restrict__ Bh,
    const float* __restrict__ bias, float* __restrict__ C,
    __half* __restrict__ Ch,
    int M, int N, int K)
{
    extern __shared__ __align__(16) char smc[];
    uint32_t sbase = smem_u32(smc);
    const uint32_t BOFF = STG * 8192;

    int t = threadIdx.x;
    int lane = t & 31, wid = t >> 5;
    int warp_m = wid & 3, warp_n = wid >> 2;
    int m0 = blockIdx.y * 128;
    int n0 = blockIdx.x * 128;

    uint32_t aOff[2];
    size_t   aG[2], bG[2];
#pragma unroll
    for (int i = 0; i < 2; i++) {
        int idx = t + i * 256;
        int row = idx >> 2, ch = idx & 3;
        uint32_t swz = (uint32_t)(ch ^ ((row >> 1) & 3));
        aOff[i] = (uint32_t)(row * 64) + swz * 16;
        aG[i] = (size_t)(m0 + row) * K + ch * 8;
        bG[i] = (size_t)(n0 + row) * K + ch * 8;
    }

    uint32_t aRow64[2]; int aRswz[2];
#pragma unroll
    for (int ti = 0; ti < 2; ti++) {
        int row = warp_m * 32 + ti * 16 + (lane & 15);
        aRow64[ti] = (uint32_t)(row * 64);
        aRswz[ti] = (row >> 1) & 3;
    }
    int aChunkBase = lane >> 4;
    uint32_t bRow64[4]; int bRswz[4];
#pragma unroll
    for (int j2 = 0; j2 < 4; j2++) {
        int row = warp_n * 64 + j2 * 16 + ((lane >> 4) << 3) + (lane & 7);
        bRow64[j2] = (uint32_t)(row * 64);
        bRswz[j2] = (row >> 1) & 3;
    }
    int bChunkBase = (lane >> 3) & 1;

    float acc[2][8][4];
#pragma unroll
    for (int mi = 0; mi < 2; mi++)
#pragma unroll
        for (int nj = 0; nj < 8; nj++)
#pragma unroll
            for (int r = 0; r < 4; r++) acc[mi][nj][r] = 0.f;

    int NC = K >> 5;

#pragma unroll
    for (int p = 0; p < 3; p++) {
        size_t ko = (size_t)p * 32;
        uint32_t sa = sbase + (uint32_t)p * 8192;
        uint32_t sb = sbase + BOFF + (uint32_t)p * 8192;
#pragma unroll
        for (int i = 0; i < 2; i++) cp16(sa + aOff[i], Ah + aG[i] + ko);
#pragma unroll
        for (int i = 0; i < 2; i++) cp16(sb + aOff[i], Bh + bG[i] + ko);
        cp_commit();
    }

    for (int c = 0; c < NC; c++) {
        cp_wait2();
        __syncthreads();

        if (c + 3 < NC) {
            size_t ko = (size_t)(c + 3) * 32;
            uint32_t st = (uint32_t)((c + 3) & (STG - 1));
            uint32_t sa = sbase + st * 8192;
            uint32_t sb = sbase + BOFF + st * 8192;
#pragma unroll
            for (int i = 0; i < 2; i++) cp16(sa + aOff[i], Ah + aG[i] + ko);
#pragma unroll
            for (int i = 0; i < 2; i++) cp16(sb + aOff[i], Bh + bG[i] + ko);
        }
        cp_commit();

        uint32_t sa = sbase + (uint32_t)(c & (STG - 1)) * 8192;
        uint32_t sb = sbase + BOFF + (uint32_t)(c & (STG - 1)) * 8192;
#pragma unroll
        for (int kstep = 0; kstep < 2; kstep++) {
            uint32_t a[2][4], b[4][4];
#pragma unroll
            for (int ti = 0; ti < 2; ti++) {
                int ch = kstep * 2 + aChunkBase;
                uint32_t addr = sa + aRow64[ti] + (uint32_t)((ch ^ aRswz[ti]) * 16);
                ldm_x4(addr, a[ti][0], a[ti][1], a[ti][2], a[ti][3]);
            }
#pragma unroll
            for (int j2 = 0; j2 < 4; j2++) {
                int ch = kstep * 2 + bChunkBase;
                uint32_t addr = sb + bRow64[j2] + (uint32_t)((ch ^ bRswz[j2]) * 16);
                ldm_x4(addr, b[j2][0], b[j2][1], b[j2][2], b[j2][3]);
            }
#pragma unroll
            for (int mi = 0; mi < 2; mi++)
#pragma unroll
                for (int nj = 0; nj < 8; nj++)
                    mma16816(acc[mi][nj], a[mi], &b[nj >> 1][(nj & 1) * 2]);
        }
    }

    int tq = lane >> 2, tr = lane & 3;
#pragma unroll
    for (int mi = 0; mi < 2; mi++) {
#pragma unroll
        for (int nj = 0; nj < 8; nj++) {
            int row0 = m0 + warp_m * 32 + mi * 16 + tq;
            int col = n0 + warp_n * 64 + nj * 8 + tr * 2;
            float b0 = __ldg(&bias[col]), b1 = __ldg(&bias[col + 1]);
            float v0 = acc[mi][nj][0] + b0, v1 = acc[mi][nj][1] + b1;
            float v2 = acc[mi][nj][2] + b0, v3 = acc[mi][nj][3] + b1;
            if (ACT) {
                v0 = 0.5f * v0 * (1.0f + erff(v0 * 0.70710678118654752f));
                v1 = 0.5f * v1 * (1.0f + erff(v1 * 0.70710678118654752f));
                v2 = 0.5f * v2 * (1.0f + erff(v2 * 0.70710678118654752f));
                v3 = 0.5f * v3 * (1.0f + erff(v3 * 0.70710678118654752f));
            }
            if (MODE == 0) {
                *(float2*)&C[(size_t)row0 * N + col] = make_float2(v0, v1);
                *(float2*)&C[(size_t)(row0 + 8) * N + col] = make_float2(v2, v3);
            } else {
                *(uint32_t*)&Ch[(size_t)row0 * N + col] = pack_h2(v0, v1);
                *(uint32_t*)&Ch[(size_t)(row0 + 8) * N + col] = pack_h2(v2, v3);
            }
        }
    }
}

// ---------------- tensor-core flash attention (fp16 in, fp16 out) ----------------
__global__ __launch_bounds__(128) void attn_mma_kernel(
    const __half* __restrict__ qk,   // [BS][2E] : Q | K
    const __half* __restrict__ v,    // [BS][E]
    __half* __restrict__ ch)         // ctx [BS][E]
{
    __shared__ __align__(16) __half q_s[64 * 64];
    __shared__ __align__(16) __half k_s[64 * 64];
    __shared__ __align__(16) __half v_s[64 * 64];

    int b = blockIdx.z, h = blockIdx.y;
    int q0 = blockIdx.x * 64;
    int t = threadIdx.x;
    int lane = t & 31, w = t >> 5;
    uint32_t sq = smem_u32(q_s), sk = smem_u32(k_s), sv = smem_u32(v_s);

#pragma unroll
    for (int i = 0; i < 4; i++) {
        int idx = t + i * 128;
        int r = idx >> 3, c = idx & 7;
        *(uint4*)((char*)q_s + r * 128 + ((c ^ (r & 7)) * 16)) =
            *(const uint4*)&qk[(size_t)(b * SS + q0 + r) * (2 * E_) + h * HD + c * 8];
    }
    __syncthreads();

    uint32_t qa[4][4];
#pragma unroll
    for (int kc = 0; kc < 4; kc++) {
        int m = lane >> 3;
        int rr = w * 16 + (lane & 7) + ((m & 1) ? 8 : 0);
        int cc = kc * 2 + (m >> 1);
        uint32_t addr = sq + (uint32_t)(rr * 128 + ((cc ^ (rr & 7)) * 16));
        ldm_x4(addr, qa[kc][0], qa[kc][1], qa[kc][2], qa[kc][3]);
    }

    float o[8][4];
#pragma unroll
    for (int d = 0; d < 8; d++)
#pragma unroll
        for (int r = 0; r < 4; r++) o[d][r] = 0.f;
    float mrow[2] = {-1e30f, -1e30f};
    float lsum[2] = {0.f, 0.f};

    int kstart = q0 - WIN; if (kstart < 0) kstart = 0;
    int kend = q0 + 64 + WIN; if (kend > SS) kend = SS;
    const float scale = 0.125f;
    int tq = lane >> 2, tr = lane & 3;

    for (int kb = kstart; kb < kend; kb += 64) {
        __syncthreads();
#pragma unroll
        for (int i = 0; i < 4; i++) {
            int idx = t + i * 128;
            int r = idx >> 3, c = idx & 7;
            uint32_t so = (uint32_t)(r * 128 + ((c ^ (r & 7)) * 16));
            *(uint4*)((char*)k_s + so) =
                *(const uint4*)&qk[(size_t)(b * SS + kb + r) * (2 * E_) + E_ + h * HD + c * 8];
            *(uint4*)((char*)v_s + so) =
                *(const uint4*)&v[(size_t)(b * SS + kb + r) * E_ + h * HD + c * 8];
        }
        __syncthreads();

        float s[8][4];
#pragma unroll
        for (int j = 0; j < 8; j++)
#pragma unroll
            for (int r = 0; r < 4; r++) s[j][r] = 0.f;
#pragma unroll
        for (int kc = 0; kc < 4; kc++) {
#pragma unroll
            for (int j2 = 0; j2 < 4; j2++) {
                int m = lane >> 3;
                int rr = j2 * 16 + (lane & 7) + ((m >= 2) ? 8 : 0);
                int cc = kc * 2 + (m & 1);
                uint32_t addr = sk + (uint32_t)(rr * 128 + ((cc ^ (rr & 7)) * 16));
                uint32_t b0, b1, b2, b3;
                ldm_x4(addr, b0, b1, b2, b3);
                uint32_t bj[2] = {b0, b1}, bj1[2] = {b2, b3};
                mma16816(s[2 * j2],     qa[kc], bj);
                mma16816(s[2 * j2 + 1], qa[kc], bj1);
            }
        }

#pragma unroll
        for (int e = 0; e < 2; e++) {
            int qi = q0 + w * 16 + tq + e * 8;
            float rmax = -1e30f;
#pragma unroll
            for (int j = 0; j < 8; j++) {
#pragma unroll
                for (int u = 0; u < 2; u++) {
                    int col = kb + j * 8 + tr * 2 + u;
                    int diff = qi - col;
                    bool ok = (diff <= WIN) && (diff >= -WIN);
                    float val = ok ? s[j][e * 2 + u] * scale : -1e30f;
                    s[j][e * 2 + u] = val;
                    rmax = fmaxf(rmax, val);
                }
            }
            rmax = fmaxf(rmax, __shfl_xor_sync(0xffffffffu, rmax, 1));
            rmax = fmaxf(rmax, __shfl_xor_sync(0xffffffffu, rmax, 2));
            float mnew = fmaxf(mrow[e], rmax);
            float corr = expf(mrow[e] - mnew);
            float rsum = 0.f;
#pragma unroll
            for (int j = 0; j < 8; j++) {
#pragma unroll
                for (int u = 0; u < 2; u++) {
                    float p = expf(s[j][e * 2 + u] - mnew);
                    s[j][e * 2 + u] = p;
                    rsum += p;
                }
            }
            rsum += __shfl_xor_sync(0xffffffffu, rsum, 1);
            rsum += __shfl_xor_sync(0xffffffffu, rsum, 2);
            mrow[e] = mnew;
            lsum[e] = lsum[e] * corr + rsum;
#pragma unroll
            for (int d = 0; d < 8; d++) {
                o[d][e * 2] *= corr;
                o[d][e * 2 + 1] *= corr;
            }
        }

#pragma unroll
        for (int kc = 0; kc < 4; kc++) {
            uint32_t pa[4];
            pa[0] = pack_h2(s[2 * kc][0],     s[2 * kc][1]);
            pa[1] = pack_h2(s[2 * kc][2],     s[2 * kc][3]);
            pa[2] = pack_h2(s[2 * kc + 1][0], s[2 * kc + 1][1]);
            pa[3] = pack_h2(s[2 * kc + 1][2], s[2 * kc + 1][3]);
#pragma unroll
            for (int d2 = 0; d2 < 4; d2++) {
                int m = lane >> 3;
                int rr = kc * 16 + (lane & 7) + ((m & 1) ? 8 : 0);
                int cc = 2 * d2 + (m >> 1);
                uint32_t addr = sv + (uint32_t)(rr * 128 + ((cc ^ (rr & 7)) * 16));
                uint32_t b0, b1, b2, b3;
                ldm_x4t(addr, b0, b1, b2, b3);
                uint32_t bd[2] = {b0, b1}, bd1[2] = {b2, b3};
                mma16816(o[2 * d2],     pa, bd);
                mma16816(o[2 * d2 + 1], pa, bd1);
            }
        }
    }

    float inv0 = 1.f / lsum[0], inv1 = 1.f / lsum[1];
#pragma unroll
    for (int d = 0; d < 8; d++) {
        int row0 = q0 + w * 16 + tq;
        int col = h * HD + d * 8 + tr * 2;
        *(uint32_t*)&ch[(size_t)(b * SS + row0) * E_ + col] =
            pack_h2(o[d][0] * inv0, o[d][1] * inv0);
        *(uint32_t*)&ch[(size_t)(b * SS + row0 + 8) * E_ + col] =
            pack_h2(o[d][2] * inv1, o[d][3] * inv1);
    }
}

// ---------------- residual add + LayerNorm (optional fused fp16 out) -------------
__global__ __launch_bounds__(256) void add_ln_kernel(
    const float* __restrict__ a, const float* __restrict__ r,
    const float* __restrict__ g, const float* __restrict__ be,
    float* __restrict__ out, __half* __restrict__ oh)
{
    int row = blockIdx.x;
    int t = threadIdx.x;
    size_t base = (size_t)row * E_;
    float4 av = *(const float4*)&a[base + t * 4];
    float4 rv = *(const float4*)&r[base + t * 4];
    float v0 = av.x + rv.x, v1 = av.y + rv.y, v2 = av.z + rv.z, v3 = av.w + rv.w;
    float sum = v0 + v1 + v2 + v3;
    float sq = v0 * v0 + v1 * v1 + v2 * v2 + v3 * v3;
#pragma unroll
    for (int off = 16; off; off >>= 1) {
        sum += __shfl_xor_sync(0xffffffffu, sum, off);
        sq  += __shfl_xor_sync(0xffffffffu, sq, off);
    }
    __shared__ float ss[8], sq2[8], stat[2];
    int w = t >> 5;
    if ((t & 31) == 0) { ss[w] = sum; sq2[w] = sq; }
    __syncthreads();
    if (t == 0) {
        float S1 = 0.f, S2 = 0.f;
        for (int i = 0; i < 8; i++) { S1 += ss[i]; S2 += sq2[i]; }
        float mean = S1 * (1.0f / E_);
        float var = S2 * (1.0f / E_) - mean * mean;
        stat[0] = mean;
        stat[1] = rsqrtf(var + 1e-5f);
    }
    __syncthreads();
    float mean = stat[0], rstd = stat[1];
    float4 gv = *(const float4*)&g[t * 4];
    float4 bv = *(const float4*)&be[t * 4];
    float o[4];
    o[0] = (v0 - mean) * rstd * gv.x + bv.x;
    o[1] = (v1 - mean) * rstd * gv.y + bv.y;
    o[2] = (v2 - mean) * rstd * gv.z + bv.z;
    o[3] = (v3 - mean) * rstd * gv.w + bv.w;
    *(float4*)&out[base + t * 4] = make_float4(o[0], o[1], o[2], o[3]);
    if (oh) {
        uint2 ho;
        ho.x = pack_h2(o[0], o[1]);
        ho.y = pack_h2(o[2], o[3]);
        *(uint2*)&oh[base + t * 4] = ho;
    }
}

// ---------------- launch ---------------------------------------------------------
extern "C" void kernel_launch(void* const* d_in, const int* in_sizes, int n_in,
                              void* d_out, int out_size)
{
    (void)in_sizes; (void)n_in; (void)out_size;
    const float* x    = (const float*)d_in[0];
    const float* ipw  = (const float*)d_in[1];
    const float* ipb  = (const float*)d_in[2];
    const float* opw  = (const float*)d_in[3];
    const float* opb  = (const float*)d_in[4];
    const float* ln1g = (const float*)d_in[5];
    const float* ln1b = (const float*)d_in[6];
    const float* w1   = (const float*)d_in[7];
    const float* b1   = (const float*)d_in[8];
    const float* w2   = (const float*)d_in[9];
    const float* b2   = (const float*)d_in[10];
    const float* ln2g = (const float*)d_in[11];
    const float* ln2b = (const float*)d_in[12];
    float* out = (float*)d_out;

    float *tmp, *x1;
    cudaGetSymbolAddress((void**)&tmp, g_tmp);
    cudaGetSymbolAddress((void**)&x1,  g_x1);

    __half *a1h, *a2h, *x1h, *hh, *qkh, *vh, *wih, *woh, *w1h, *w2h;
    cudaGetSymbolAddress((void**)&a1h, g_a1h);
    cudaGetSymbolAddress((void**)&a2h, g_a2h);
    cudaGetSymbolAddress((void**)&x1h, g_x1h);
    cudaGetSymbolAddress((void**)&hh,  g_hh);
    cudaGetSymbolAddress((void**)&qkh, g_qkh);
    cudaGetSymbolAddress((void**)&vh,  g_vh);
    cudaGetSymbolAddress((void**)&wih, g_wih); cudaGetSymbolAddress((void**)&woh, g_woh);
    cudaGetSymbolAddress((void**)&w1h, g_w1h); cudaGetSymbolAddress((void**)&w2h, g_w2h);

    cudaFuncSetAttribute(gemm_mma_kernel<0,0>,
                         cudaFuncAttributeMaxDynamicSharedMemorySize, GEMM_SMEM);
    cudaFuncSetAttribute(gemm_mma_kernel<0,1>,
                         cudaFuncAttributeMaxDynamicSharedMemorySize, GEMM_SMEM);
    cudaFuncSetAttribute(gemm_mma_kernel<1,1>,
                         cudaFuncAttributeMaxDynamicSharedMemorySize, GEMM_SMEM);

    cudaStream_t s0 = 0, s2 = g_sp.s2;

    // fork second stream from the capture stream
    cudaEventRecord(g_sp.eStart, s0);
    cudaStreamWaitEvent(s2, g_sp.eStart, 0);

    // 0: RoPE(x) -> a1h, and plain fp16 x -> a2h   (s0)
    rope_conv_kernel<<<BS, 256, 0, s0>>>(x, a1h, a2h);
    cudaEventRecord(g_sp.eR, s0);

    // 1: in_proj weight conv (s2)
    conv_kernel<<<(3 * E_ * E_) / 1024, 256, 0, s2>>>(ipw, wih);
    cudaEventRecord(g_sp.eWih, s2);

    // 2: fused Q|K GEMM (s0, needs wih)
    cudaStreamWaitEvent(s0, g_sp.eWih, 0);
    gemm_mma_kernel<0,1><<<dim3(16, 64), 256, GEMM_SMEM, s0>>>(
        a1h, wih, ipb, nullptr, qkh, BS, 2 * E_, E_);

    // 3: V GEMM (s2, needs a2h)
    cudaStreamWaitEvent(s2, g_sp.eR, 0);
    gemm_mma_kernel<0,1><<<dim3(8, 64), 256, GEMM_SMEM, s2>>>(
        a2h, wih + (size_t)2*E_*E_, ipb + 2 * E_, nullptr, vh, BS, E_, E_);
    cudaEventRecord(g_sp.eV, s2);

    // 4: out_proj weight conv (s2)
    conv_kernel<<<(E_ * E_) / 1024, 256, 0, s2>>>(opw, woh);

    // 5: tensor-core attention (s0, needs V)  -> ctx into a2h
    cudaStreamWaitEvent(s0, g_sp.eV, 0);
    attn_mma_kernel<<<dim3(SS / 64, NH, BB), 128, 0, s0>>>(qkh, vh, a2h);

    // 6,7: FFN weight convs (s2)
    conv_kernel<<<(FF * E_) / 1024, 256, 0, s2>>>(w1, w1h);
    conv_kernel<<<(FF * E_) / 1024, 256, 0, s2>>>(w2, w2h);
    cudaEventRecord(g_sp.eW2, s2);

    // join: everything downstream on s0
    cudaStreamWaitEvent(s0, g_sp.eW2, 0);

    // 8: out-proj GEMM; 9: LN1
    gemm_mma_kernel<0,0><<<dim3(8, 64), 256, GEMM_SMEM, s0>>>(
        a2h, woh, opb, tmp, nullptr, BS, E_, E_);
    add_ln_kernel<<<BS, 256, 0, s0>>>(x, tmp, ln1g, ln1b, x1, x1h);

    // 10-12: FFN + LN2
    gemm_mma_kernel<1,1><<<dim3(32, 64), 256, GEMM_SMEM, s0>>>(
        x1h, w1h, b1, nullptr, hh, BS, FF, E_);
    gemm_mma_kernel<0,0><<<dim3(8, 64), 256, GEMM_SMEM, s0>>>(
        hh, w2h, b2, tmp, nullptr, BS, E_, FF);
    add_ln_kernel<<<BS, 256, 0, s0>>>(x1, tmp, ln2g, ln2b, out, nullptr);
}